// round 3
// baseline (speedup 1.0000x reference)
#include <cuda_runtime.h>
#include <math.h>

// Problem constants
#define BB   128
#define TT   1024
#define DD   128
#define HH   256
#define G4H  1024

// Scan decomposition: 4 batch-groups x 32 N-slice CTAs = 128 CTAs
#define NBG  4
#define NNC  32
#define BSUB 32          // batch rows per CTA  (128/4)
#define HC   8           // h columns per CTA   (256/32)
#define NR   32          // gate rows per CTA   (4 gates * HC)
#define NTHREADS 256

// Device scratch (static — no allocation allowed)
__device__ float    g_Y0[BB * TT * HH];   // 128 MB ping
__device__ float    g_Y1[BB * TT * HH];   // 128 MB pong
__device__ float    g_h[2][BB * HH];      // h double buffer (parity = step index)
__device__ unsigned g_ctr[NBG];           // per-batch-group monotonic barrier counters

__global__ void reset_kernel() {
    if (threadIdx.x < NBG) g_ctr[threadIdx.x] = 0u;
}

__device__ __forceinline__ float fma4(float acc, float4 u, float4 w) {
    acc = fmaf(u.x, w.x, acc);
    acc = fmaf(u.y, w.y, acc);
    acc = fmaf(u.z, w.z, acc);
    acc = fmaf(u.w, w.w, acc);
    return acc;
}

// One LSTM layer scan. KIN = input feature width (128 for layer 0, 256 after).
// Xsrc layout: [B, T, KIN]. Output written to g_Y0/g_Y1 per ysel, layout [B, T, H].
template <int KIN>
__global__ void __launch_bounds__(NTHREADS, 1)
lstm_scan_kernel(const float* __restrict__ xext, int xsel, int ysel,
                 const float* __restrict__ Wih,   // [4H, KIN]
                 const float* __restrict__ Whh,   // [4H, H]
                 const float* __restrict__ bih,   // [4H]
                 const float* __restrict__ bhh)   // [4H]
{
    constexpr int KTOT = KIN + HH;
    constexpr int STR  = KTOT + 4;      // padded row stride (floats), 16B-aligned rows

    extern __shared__ float sm[];
    float* Wsm = sm;                         // [NR][STR]   weight slab (resident whole scan)
    float* Usm = Wsm + NR * STR;             // [BSUB][STR] concat {x_t, h_{t-1}}
    float* Gsm = Usm + BSUB * STR;           // [BSUB][NR+1] gate pre-activations
    float* Bsm = Gsm + BSUB * (NR + 1);      // [NR] bias

    const float* Xsrc = (xsel == 0) ? xext : ((xsel == 1) ? g_Y0 : g_Y1);
    float*       Ydst = (ysel == 0) ? g_Y0 : g_Y1;

    const int cta = blockIdx.x;
    const int bg  = cta / NNC;          // batch group 0..3
    const int nc  = cta % NNC;          // N-slice 0..31
    const int rb0 = bg * BSUB;          // first batch row
    const int hc0 = nc * HC;            // first h column
    const int tid = threadIdx.x;

    // ---- Load weight slab once: gate-local row rl = g*8 + j -> global row g*H + hc0 + j
    for (int idx = tid; idx < NR * KTOT; idx += NTHREADS) {
        int rl = idx / KTOT;
        int k  = idx - rl * KTOT;
        int g  = rl >> 3, j = rl & 7;
        int rg = g * HH + hc0 + j;
        float w = (k < KIN) ? Wih[(size_t)rg * KIN + k]
                            : Whh[(size_t)rg * HH + (k - KIN)];
        Wsm[rl * STR + k] = w;
    }
    if (tid < NR) {
        int g = tid >> 3, j = tid & 7;
        int rg = g * HH + hc0 + j;
        Bsm[tid] = bih[rg] + bhh[rg];
    }

    // GEMM thread mapping: 16x16 threads, each computes a 2x2 output micro-tile
    const int ty = tid >> 4, tx = tid & 15;
    const int b0 = ty * 2, b1 = b0 + 1;
    const int r0 = tx * 2, r1 = r0 + 1;
    // Activation-phase mapping: thread owns (batch=myb, hcol=myj); c lives in a register
    const int myb = tid >> 3, myj = tid & 7;
    float c_state = 0.0f;

    unsigned target = 0;

    for (int t = 0; t < TT; ++t) {
        __syncthreads();   // covers weight-load (t=0) and protects Usm/Gsm reuse

        // ---- Stage x_t slice [BSUB, KIN]
        for (int idx = tid * 4; idx < BSUB * KIN; idx += NTHREADS * 4) {
            int b = idx / KIN, k = idx - b * KIN;
            float4 v = *reinterpret_cast<const float4*>(
                Xsrc + ((size_t)(rb0 + b) * TT + t) * KIN + k);
            *reinterpret_cast<float4*>(&Usm[b * STR + k]) = v;
        }
        // ---- Stage h_{t-1} slice [BSUB, H] (L2-only loads: cross-CTA data)
        if (t == 0) {
            for (int idx = tid * 4; idx < BSUB * HH; idx += NTHREADS * 4) {
                int b = idx / HH, k = idx - b * HH;
                *reinterpret_cast<float4*>(&Usm[b * STR + KIN + k]) =
                    make_float4(0.f, 0.f, 0.f, 0.f);
            }
        } else {
            const float* hsrc = g_h[t & 1];
            for (int idx = tid * 4; idx < BSUB * HH; idx += NTHREADS * 4) {
                int b = idx / HH, k = idx - b * HH;
                float4 v = __ldcg(reinterpret_cast<const float4*>(
                    hsrc + (size_t)(rb0 + b) * HH + k));
                *reinterpret_cast<float4*>(&Usm[b * STR + KIN + k]) = v;
            }
        }
        __syncthreads();

        // ---- 32x32 GEMM over K = KIN + H
        float a00 = 0.f, a01 = 0.f, a10 = 0.f, a11 = 0.f;
        const float4* u0p = reinterpret_cast<const float4*>(&Usm[b0 * STR]);
        const float4* u1p = reinterpret_cast<const float4*>(&Usm[b1 * STR]);
        const float4* w0p = reinterpret_cast<const float4*>(&Wsm[r0 * STR]);
        const float4* w1p = reinterpret_cast<const float4*>(&Wsm[r1 * STR]);
#pragma unroll 8
        for (int k4 = 0; k4 < KTOT / 4; ++k4) {
            float4 u0 = u0p[k4], u1 = u1p[k4];
            float4 w0 = w0p[k4], w1 = w1p[k4];
            a00 = fma4(a00, u0, w0);
            a01 = fma4(a01, u0, w1);
            a10 = fma4(a10, u1, w0);
            a11 = fma4(a11, u1, w1);
        }
        Gsm[b0 * (NR + 1) + r0] = a00 + Bsm[r0];
        Gsm[b0 * (NR + 1) + r1] = a01 + Bsm[r1];
        Gsm[b1 * (NR + 1) + r0] = a10 + Bsm[r0];
        Gsm[b1 * (NR + 1) + r1] = a11 + Bsm[r1];
        __syncthreads();

        // ---- Gate nonlinearities + state update (PyTorch order i,f,g,o)
        {
            float iv = Gsm[myb * (NR + 1) + 0  + myj];
            float fv = Gsm[myb * (NR + 1) + 8  + myj];
            float gv = Gsm[myb * (NR + 1) + 16 + myj];
            float ov = Gsm[myb * (NR + 1) + 24 + myj];
            float is = 1.f / (1.f + expf(-iv));
            float fs = 1.f / (1.f + expf(-fv));
            float gt = tanhf(gv);
            float os = 1.f / (1.f + expf(-ov));
            c_state = fs * c_state + is * gt;
            float hn = os * tanhf(c_state);
            int bglob = rb0 + myb;
            g_h[(t + 1) & 1][(size_t)bglob * HH + hc0 + myj] = hn;
            Ydst[((size_t)bglob * TT + t) * HH + hc0 + myj]  = hn;
        }

        // ---- Batch-group barrier (monotonic counter, release/acquire via L2)
        __threadfence();
        __syncthreads();
        target += NNC;
        if (tid == 0) {
            atomicAdd(&g_ctr[bg], 1u);
            while (atomicAdd(&g_ctr[bg], 0u) < target) { __nanosleep(64); }
            __threadfence();
        }
        __syncthreads();
    }
}

// Final FC: out[b*T + t] = dot(Y0[b,t,:], fc_W) + fc_b. One warp per row.
__global__ void __launch_bounds__(256)
fc_kernel(const float* __restrict__ w, const float* __restrict__ bptr,
          float* __restrict__ out)
{
    int row  = blockIdx.x * 8 + (threadIdx.x >> 5);
    int lane = threadIdx.x & 31;
    const float* yr = g_Y0 + (size_t)row * HH;
    float4 a0 = *reinterpret_cast<const float4*>(yr + lane * 4);
    float4 a1 = *reinterpret_cast<const float4*>(yr + 128 + lane * 4);
    float4 w0 = *reinterpret_cast<const float4*>(w + lane * 4);
    float4 w1 = *reinterpret_cast<const float4*>(w + 128 + lane * 4);
    float s = a0.x * w0.x + a0.y * w0.y + a0.z * w0.z + a0.w * w0.w
            + a1.x * w1.x + a1.y * w1.y + a1.z * w1.z + a1.w * w1.w;
#pragma unroll
    for (int off = 16; off > 0; off >>= 1)
        s += __shfl_xor_sync(0xffffffffu, s, off);
    if (lane == 0) out[row] = s + bptr[0];
}

static inline size_t scan_smem_bytes(int kin) {
    int ktot = kin + HH;
    int str  = ktot + 4;
    return (size_t)(NR * str + BSUB * str + BSUB * (NR + 1) + NR) * sizeof(float);
}

extern "C" void kernel_launch(void* const* d_in, const int* in_sizes, int n_in,
                              void* d_out, int out_size)
{
    const float* x        = (const float*)d_in[0];
    const float* Wih0     = (const float*)d_in[1];
    const float* Whh0     = (const float*)d_in[2];
    const float* Wih_rest = (const float*)d_in[3];
    const float* Whh_rest = (const float*)d_in[4];
    const float* bih      = (const float*)d_in[5];
    const float* bhh      = (const float*)d_in[6];
    const float* fcW      = (const float*)d_in[7];
    const float* fcb      = (const float*)d_in[8];
    float* out = (float*)d_out;

    size_t smem0 = scan_smem_bytes(DD);   // ~103.7 KB
    size_t smem1 = scan_smem_bytes(HH);   // ~136.4 KB
    cudaFuncSetAttribute(lstm_scan_kernel<DD>,
                         cudaFuncAttributeMaxDynamicSharedMemorySize, (int)smem0);
    cudaFuncSetAttribute(lstm_scan_kernel<HH>,
                         cudaFuncAttributeMaxDynamicSharedMemorySize, (int)smem1);

    dim3 grid(NBG * NNC);

    // Layer 0: x (KIN=128) -> Y0
    reset_kernel<<<1, 32>>>();
    lstm_scan_kernel<DD><<<grid, NTHREADS, smem0>>>(
        x, /*xsel=*/0, /*ysel=*/0, Wih0, Whh0, bih + 0 * G4H, bhh + 0 * G4H);

    // Layers 1..4: ping-pong Y0 <-> Y1 (l odd writes Y1, l even writes Y0)
    for (int l = 1; l <= 4; ++l) {
        int xsel = ((l - 1) & 1) == 0 ? 1 : 2;   // read Y0 for l=1,3 ; Y1 for l=2,4
        int ysel = (l & 1);                      // write Y1 for l=1,3 ; Y0 for l=2,4
        const float* Wih = Wih_rest + (size_t)(l - 1) * G4H * HH;
        const float* Whh = Whh_rest + (size_t)(l - 1) * G4H * HH;
        reset_kernel<<<1, 32>>>();
        lstm_scan_kernel<HH><<<grid, NTHREADS, smem1>>>(
            nullptr, xsel, ysel, Wih, Whh, bih + (size_t)l * G4H, bhh + (size_t)l * G4H);
    }

    // Final layer (l=4) wrote Y0. FC head: [B*T] rows, one warp each.
    fc_kernel<<<(BB * TT) / 8, 256>>>(fcW, fcb, out);
}

// round 4
// speedup vs baseline: 2.2877x; 2.2877x over previous
#include <cuda_runtime.h>
#include <stdint.h>
#include <math.h>

// Problem constants
#define BB   128
#define TT   1024
#define DD   128
#define HH   256
#define G4H  1024

// Scan decomposition: 4 batch-groups x 32 N-slice CTAs = 128 CTAs
#define NBG  4
#define NNC  32
#define BSUB 32          // batch rows per CTA  (128/4)
#define HC   8           // h columns per CTA   (256/32)
#define NR   32          // gate rows per CTA   (4 gates * HC)
#define NTHREADS 256
#define GSTR 33          // Gsm row stride

// Device scratch (static — no allocation allowed)
__device__ float    g_Y0[BB * TT * HH];   // 128 MB ping
__device__ float    g_Y1[BB * TT * HH];   // 128 MB pong
__device__ float    g_h[2][BB * HH];      // h double buffer (parity = step index)
__device__ unsigned g_ctr[NBG];           // per-batch-group monotonic barrier counters

__global__ void reset_kernel() {
    if (threadIdx.x < NBG) g_ctr[threadIdx.x] = 0u;
}

__device__ __forceinline__ float to_tf32(float x) {
    float r;
    asm("cvt.rna.tf32.f32 %0, %1;" : "=f"(r) : "f"(x));
    return r;
}

__device__ __forceinline__ void mma_tf32(float& c0, float& c1, float& c2, float& c3,
                                         uint32_t a0, uint32_t a1, uint32_t a2, uint32_t a3,
                                         uint32_t b0, uint32_t b1) {
    asm volatile(
        "mma.sync.aligned.m16n8k8.row.col.f32.tf32.tf32.f32 "
        "{%0,%1,%2,%3}, {%4,%5,%6,%7}, {%8,%9}, {%0,%1,%2,%3};\n"
        : "+f"(c0), "+f"(c1), "+f"(c2), "+f"(c3)
        : "r"(a0), "r"(a1), "r"(a2), "r"(a3), "r"(b0), "r"(b1));
}

// One LSTM layer scan with tensor-core (tf32) per-step GEMM.
// KIN = input feature width (128 for layer 0, 256 after).
// Xsrc layout: [B, T, KIN]. Output written to g_Y0/g_Y1 per ysel, layout [B, T, H].
template <int KIN>
__global__ void __launch_bounds__(NTHREADS, 1)
lstm_scan_kernel(const float* __restrict__ xext, int xsel, int ysel,
                 const float* __restrict__ Wih,   // [4H, KIN]
                 const float* __restrict__ Whh,   // [4H, H]
                 const float* __restrict__ bih,   // [4H]
                 const float* __restrict__ bhh)   // [4H]
{
    constexpr int KTOT = KIN + HH;
    constexpr int KT8  = KTOT / 8;
    constexpr int STR  = KTOT + 4;      // padded row stride (floats); STR % 32 == 4

    extern __shared__ float sm[];
    float* Wsm = sm;                         // [NR][STR]   weight slab (tf32-rounded, resident)
    float* Usm = Wsm + NR * STR;             // [BSUB][STR] concat {x_t, h_{t-1}} (tf32-rounded)
    float* Gsm = Usm + BSUB * STR;           // [BSUB][GSTR] gate pre-activations (fp32)
    float* Bsm = Gsm + BSUB * GSTR;          // [NR] bias (fp32)

    const float* Xsrc = (xsel == 0) ? xext : ((xsel == 1) ? g_Y0 : g_Y1);
    float*       Ydst = (ysel == 0) ? g_Y0 : g_Y1;

    const int cta = blockIdx.x;
    const int bg  = cta / NNC;          // batch group 0..3
    const int nc  = cta % NNC;          // N-slice 0..31
    const int rb0 = bg * BSUB;          // first batch row
    const int hc0 = nc * HC;            // first h column
    const int tid = threadIdx.x;

    // ---- Load weight slab once (tf32-rounded): rl = g*8 + j -> global row g*H + hc0 + j
    for (int idx = tid; idx < NR * KTOT; idx += NTHREADS) {
        int rl = idx / KTOT;
        int k  = idx - rl * KTOT;
        int gg = rl >> 3, j = rl & 7;
        int rg = gg * HH + hc0 + j;
        float w = (k < KIN) ? Wih[(size_t)rg * KIN + k]
                            : Whh[(size_t)rg * HH + (k - KIN)];
        Wsm[rl * STR + k] = to_tf32(w);
    }
    if (tid < NR) {
        int gg = tid >> 3, j = tid & 7;
        int rg = gg * HH + hc0 + j;
        Bsm[tid] = bih[rg] + bhh[rg];
    }

    // ---- MMA thread mapping: 8 warps = 2(m) x 4(n); warp tile m16 x n8, full K
    const int lane = tid & 31;
    const int wid  = tid >> 5;
    const int wm   = wid >> 2;          // 0..1  (batch half)
    const int wn   = wid & 3;           // 0..3  (gate-row octet = gate index)
    const int grp  = lane >> 2;         // 0..7
    const int tg   = lane & 3;          // 0..3

    // Fragment base pointers (conflict-free: STR % 32 == 4)
    const uint32_t* Ar0 = reinterpret_cast<const uint32_t*>(&Usm[(wm * 16 + grp) * STR + tg]);
    const uint32_t* Ar1 = Ar0 + 8 * STR;
    const uint32_t* Br  = reinterpret_cast<const uint32_t*>(&Wsm[(wn * 8 + grp) * STR + tg]);

    // Gsm write targets for this thread's accumulators
    float* Gw0 = &Gsm[(wm * 16 + grp) * GSTR + wn * 8 + tg * 2];
    float* Gw1 = Gw0 + 8 * GSTR;
    const float bs0 = 0.f; (void)bs0;

    // Activation-phase mapping: thread owns (batch=myb, hcol=myj); c lives in a register
    const int myb = tid >> 3, myj = tid & 7;
    float c_state = 0.0f;

    unsigned target = 0;

    for (int t = 0; t < TT; ++t) {
        __syncthreads();   // covers weight-load (t=0) and protects Usm/Gsm reuse

        // ---- Stage x_t slice [BSUB, KIN] (tf32-rounded)
        for (int idx = tid * 4; idx < BSUB * KIN; idx += NTHREADS * 4) {
            int b = idx / KIN, k = idx - b * KIN;
            float4 v = *reinterpret_cast<const float4*>(
                Xsrc + ((size_t)(rb0 + b) * TT + t) * KIN + k);
            v.x = to_tf32(v.x); v.y = to_tf32(v.y);
            v.z = to_tf32(v.z); v.w = to_tf32(v.w);
            *reinterpret_cast<float4*>(&Usm[b * STR + k]) = v;
        }
        // ---- Stage h_{t-1} slice [BSUB, H] (L2 loads, tf32-rounded)
        if (t == 0) {
            for (int idx = tid * 4; idx < BSUB * HH; idx += NTHREADS * 4) {
                int b = idx / HH, k = idx - b * HH;
                *reinterpret_cast<float4*>(&Usm[b * STR + KIN + k]) =
                    make_float4(0.f, 0.f, 0.f, 0.f);
            }
        } else {
            const float* hsrc = g_h[t & 1];
            for (int idx = tid * 4; idx < BSUB * HH; idx += NTHREADS * 4) {
                int b = idx / HH, k = idx - b * HH;
                float4 v = __ldcg(reinterpret_cast<const float4*>(
                    hsrc + (size_t)(rb0 + b) * HH + k));
                v.x = to_tf32(v.x); v.y = to_tf32(v.y);
                v.z = to_tf32(v.z); v.w = to_tf32(v.w);
                *reinterpret_cast<float4*>(&Usm[b * STR + KIN + k]) = v;
            }
        }
        __syncthreads();

        // ---- Tensor-core GEMM: warp computes m16 x n8 over K = KTOT
        float c0 = 0.f, c1 = 0.f, c2 = 0.f, c3 = 0.f;
#pragma unroll 8
        for (int kt = 0; kt < KT8; ++kt) {
            uint32_t a0 = Ar0[kt * 8];
            uint32_t a1 = Ar1[kt * 8];
            uint32_t a2 = Ar0[kt * 8 + 4];
            uint32_t a3 = Ar1[kt * 8 + 4];
            uint32_t b0 = Br [kt * 8];
            uint32_t b1 = Br [kt * 8 + 4];
            mma_tf32(c0, c1, c2, c3, a0, a1, a2, a3, b0, b1);
        }
        {
            int col = wn * 8 + tg * 2;
            float bb0 = Bsm[col], bb1 = Bsm[col + 1];
            Gw0[0] = c0 + bb0;
            Gw0[1] = c1 + bb1;
            Gw1[0] = c2 + bb0;
            Gw1[1] = c3 + bb1;
        }
        __syncthreads();

        // ---- Gate nonlinearities + state update (PyTorch order i,f,g,o)
        {
            float iv = Gsm[myb * GSTR + 0  + myj];
            float fv = Gsm[myb * GSTR + 8  + myj];
            float gv = Gsm[myb * GSTR + 16 + myj];
            float ov = Gsm[myb * GSTR + 24 + myj];
            float is = 1.f / (1.f + expf(-iv));
            float fs = 1.f / (1.f + expf(-fv));
            float gt = tanhf(gv);
            float os = 1.f / (1.f + expf(-ov));
            c_state = fs * c_state + is * gt;
            float hn = os * tanhf(c_state);
            int bglob = rb0 + myb;
            g_h[(t + 1) & 1][(size_t)bglob * HH + hc0 + myj] = hn;
            Ydst[((size_t)bglob * TT + t) * HH + hc0 + myj]  = hn;
        }

        // ---- Batch-group barrier (monotonic counter, release/acquire via L2)
        __threadfence();
        __syncthreads();
        target += NNC;
        if (tid == 0) {
            atomicAdd(&g_ctr[bg], 1u);
            while (atomicAdd(&g_ctr[bg], 0u) < target) { __nanosleep(64); }
            __threadfence();
        }
        __syncthreads();
    }
}

// Final FC: out[b*T + t] = dot(Y0[b,t,:], fc_W) + fc_b. One warp per row.
__global__ void __launch_bounds__(256)
fc_kernel(const float* __restrict__ w, const float* __restrict__ bptr,
          float* __restrict__ out)
{
    int row  = blockIdx.x * 8 + (threadIdx.x >> 5);
    int lane = threadIdx.x & 31;
    const float* yr = g_Y0 + (size_t)row * HH;
    float4 a0 = *reinterpret_cast<const float4*>(yr + lane * 4);
    float4 a1 = *reinterpret_cast<const float4*>(yr + 128 + lane * 4);
    float4 w0 = *reinterpret_cast<const float4*>(w + lane * 4);
    float4 w1 = *reinterpret_cast<const float4*>(w + 128 + lane * 4);
    float s = a0.x * w0.x + a0.y * w0.y + a0.z * w0.z + a0.w * w0.w
            + a1.x * w1.x + a1.y * w1.y + a1.z * w1.z + a1.w * w1.w;
#pragma unroll
    for (int off = 16; off > 0; off >>= 1)
        s += __shfl_xor_sync(0xffffffffu, s, off);
    if (lane == 0) out[row] = s + bptr[0];
}

static inline size_t scan_smem_bytes(int kin) {
    int ktot = kin + HH;
    int str  = ktot + 4;
    return (size_t)(NR * str + BSUB * str + BSUB * GSTR + NR) * sizeof(float);
}

extern "C" void kernel_launch(void* const* d_in, const int* in_sizes, int n_in,
                              void* d_out, int out_size)
{
    const float* x        = (const float*)d_in[0];
    const float* Wih0     = (const float*)d_in[1];
    const float* Whh0     = (const float*)d_in[2];
    const float* Wih_rest = (const float*)d_in[3];
    const float* Whh_rest = (const float*)d_in[4];
    const float* bih      = (const float*)d_in[5];
    const float* bhh      = (const float*)d_in[6];
    const float* fcW      = (const float*)d_in[7];
    const float* fcb      = (const float*)d_in[8];
    float* out = (float*)d_out;

    size_t smem0 = scan_smem_bytes(DD);   // ~104 KB
    size_t smem1 = scan_smem_bytes(HH);   // ~137 KB
    cudaFuncSetAttribute(lstm_scan_kernel<DD>,
                         cudaFuncAttributeMaxDynamicSharedMemorySize, (int)smem0);
    cudaFuncSetAttribute(lstm_scan_kernel<HH>,
                         cudaFuncAttributeMaxDynamicSharedMemorySize, (int)smem1);

    dim3 grid(NBG * NNC);

    // Layer 0: x (KIN=128) -> Y0
    reset_kernel<<<1, 32>>>();
    lstm_scan_kernel<DD><<<grid, NTHREADS, smem0>>>(
        x, /*xsel=*/0, /*ysel=*/0, Wih0, Whh0, bih + 0 * G4H, bhh + 0 * G4H);

    // Layers 1..4: ping-pong Y0 <-> Y1 (l odd writes Y1, l even writes Y0)
    for (int l = 1; l <= 4; ++l) {
        int xsel = ((l - 1) & 1) == 0 ? 1 : 2;   // read Y0 for l=1,3 ; Y1 for l=2,4
        int ysel = (l & 1);                      // write Y1 for l=1,3 ; Y0 for l=2,4
        const float* Wih = Wih_rest + (size_t)(l - 1) * G4H * HH;
        const float* Whh = Whh_rest + (size_t)(l - 1) * G4H * HH;
        reset_kernel<<<1, 32>>>();
        lstm_scan_kernel<HH><<<grid, NTHREADS, smem1>>>(
            nullptr, xsel, ysel, Wih, Whh, bih + (size_t)l * G4H, bhh + (size_t)l * G4H);
    }

    // Final layer (l=4) wrote Y0. FC head: [B*T] rows, one warp each.
    fc_kernel<<<(BB * TT) / 8, 256>>>(fcW, fcb, out);
}

// round 5
// speedup vs baseline: 2.5245x; 1.1035x over previous
#include <cuda_runtime.h>
#include <stdint.h>
#include <math.h>

// Problem constants
#define BB   128
#define TT   1024
#define DD   128
#define HH   256
#define G4H  1024

// Scan decomposition: 4 batch-groups x 32 N-slice CTAs = 128 CTAs
#define NBG  4
#define NNC  32
#define BSUB 32          // batch rows per CTA  (128/4)
#define HC   8           // h columns per CTA   (256/32)
#define NR   32          // gate rows per CTA (j-major: col p = j_local*4 + gate)
#define NTHREADS 256

// Device scratch (static — no allocation allowed)
__device__ float    g_XG[(size_t)BB * TT * G4H]; // 512 MB precomputed input gates (+bias)
__device__ float    g_Y0[(size_t)BB * TT * HH];  // 128 MB ping
__device__ float    g_Y1[(size_t)BB * TT * HH];  // 128 MB pong
__device__ float    g_h[2][BB * HH];             // h double buffer (parity = step index)
__device__ unsigned g_ctr[NBG];                  // per-batch-group barrier counters

__global__ void reset_kernel() {
    if (threadIdx.x < NBG) g_ctr[threadIdx.x] = 0u;
}

__device__ __forceinline__ float to_tf32(float x) {
    float r;
    asm("cvt.rna.tf32.f32 %0, %1;" : "=f"(r) : "f"(x));
    return r;
}

__device__ __forceinline__ void mma_tf32(float& c0, float& c1, float& c2, float& c3,
                                         uint32_t a0, uint32_t a1, uint32_t a2, uint32_t a3,
                                         uint32_t b0, uint32_t b1) {
    asm volatile(
        "mma.sync.aligned.m16n8k8.row.col.f32.tf32.tf32.f32 "
        "{%0,%1,%2,%3}, {%4,%5,%6,%7}, {%8,%9}, {%0,%1,%2,%3};\n"
        : "+f"(c0), "+f"(c1), "+f"(c2), "+f"(c3)
        : "r"(a0), "r"(a1), "r"(a2), "r"(a3), "r"(b0), "r"(b1));
}

// ============================================================================
// xg GEMM: g_XG[m, P] = sum_k In[m,k] * Wih[perm(P), k] + bih[perm(P)] + bhh[...]
// Column order P is j-major permuted: P = j_global*4 + gate; perm(P) = (P&3)*HH + (P>>2).
// CTA tile 128(m) x 64(n), full K resident in smem. 8 warps = 4(m) x 2(n), warp m32n32.
// ============================================================================
template <int K>
__global__ void __launch_bounds__(256, 1)
xg_gemm_kernel(const float* __restrict__ xext, int xsel,
               const float* __restrict__ Wih,
               const float* __restrict__ bih, const float* __restrict__ bhh)
{
    constexpr int KS = K + 4;                 // padded stride; KS % 32 == 4
    extern __shared__ float sm[];
    float* As   = sm;                         // [128][KS]
    float* Bs   = As + 128 * KS;              // [64][KS]
    float* bias = Bs + 64 * KS;               // [64]

    const float* In = (xsel == 0) ? xext : ((xsel == 1) ? g_Y0 : g_Y1);
    const int m0  = blockIdx.y * 128;
    const int n0  = blockIdx.x * 64;
    const int tid = threadIdx.x;

    for (int idx = tid; idx < 128 * (K / 4); idx += 256) {
        int r = idx / (K / 4), k4 = idx - r * (K / 4);
        float4 v = *reinterpret_cast<const float4*>(In + (size_t)(m0 + r) * K + k4 * 4);
        v.x = to_tf32(v.x); v.y = to_tf32(v.y); v.z = to_tf32(v.z); v.w = to_tf32(v.w);
        *reinterpret_cast<float4*>(&As[r * KS + k4 * 4]) = v;
    }
    for (int idx = tid; idx < 64 * (K / 4); idx += 256) {
        int n = idx / (K / 4), k4 = idx - n * (K / 4);
        int P  = n0 + n;
        int rw = (P & 3) * HH + (P >> 2);
        float4 v = *reinterpret_cast<const float4*>(Wih + (size_t)rw * K + k4 * 4);
        v.x = to_tf32(v.x); v.y = to_tf32(v.y); v.z = to_tf32(v.z); v.w = to_tf32(v.w);
        *reinterpret_cast<float4*>(&Bs[n * KS + k4 * 4]) = v;
    }
    if (tid < 64) {
        int P  = n0 + tid;
        int bx = (P & 3) * HH + (P >> 2);
        bias[tid] = bih[bx] + bhh[bx];
    }
    __syncthreads();

    const int lane = tid & 31, wid = tid >> 5;
    const int wm = wid >> 1, wn = wid & 1;
    const int grp = lane >> 2, tg = lane & 3;

    float acc[2][4][4];
#pragma unroll
    for (int mi = 0; mi < 2; ++mi)
#pragma unroll
        for (int ni = 0; ni < 4; ++ni)
#pragma unroll
            for (int q = 0; q < 4; ++q) acc[mi][ni][q] = 0.f;

    const uint32_t* Ap0 = reinterpret_cast<const uint32_t*>(&As[(wm * 32 + grp) * KS + tg]);
    const uint32_t* Bp0 = reinterpret_cast<const uint32_t*>(&Bs[(wn * 32 + grp) * KS + tg]);

#pragma unroll 4
    for (int kt = 0; kt < K / 8; ++kt) {
        uint32_t a[2][4], bf[4][2];
#pragma unroll
        for (int mi = 0; mi < 2; ++mi) {
            const uint32_t* p = Ap0 + mi * 16 * KS + kt * 8;
            a[mi][0] = p[0]; a[mi][1] = p[8 * KS]; a[mi][2] = p[4]; a[mi][3] = p[8 * KS + 4];
        }
#pragma unroll
        for (int ni = 0; ni < 4; ++ni) {
            const uint32_t* p = Bp0 + ni * 8 * KS + kt * 8;
            bf[ni][0] = p[0]; bf[ni][1] = p[4];
        }
#pragma unroll
        for (int mi = 0; mi < 2; ++mi)
#pragma unroll
            for (int ni = 0; ni < 4; ++ni)
                mma_tf32(acc[mi][ni][0], acc[mi][ni][1], acc[mi][ni][2], acc[mi][ni][3],
                         a[mi][0], a[mi][1], a[mi][2], a[mi][3], bf[ni][0], bf[ni][1]);
    }

#pragma unroll
    for (int mi = 0; mi < 2; ++mi)
#pragma unroll
        for (int ni = 0; ni < 4; ++ni) {
            int rl = wm * 32 + mi * 16 + grp;
            int cl = wn * 32 + ni * 8 + 2 * tg;
            float b0 = bias[cl], b1 = bias[cl + 1];
            size_t o = (size_t)(m0 + rl) * G4H + (n0 + cl);
            *reinterpret_cast<float2*>(&g_XG[o]) =
                make_float2(acc[mi][ni][0] + b0, acc[mi][ni][1] + b1);
            *reinterpret_cast<float2*>(&g_XG[o + (size_t)8 * G4H]) =
                make_float2(acc[mi][ni][2] + b0, acc[mi][ni][3] + b1);
        }
}

// ============================================================================
// LSTM scan: per step only Whh*h via tensor cores; xg preloaded into accumulators.
// Weight slab rows in j-major gate order: row p = j_local*4 + gate.
// ============================================================================
__global__ void __launch_bounds__(NTHREADS, 1)
lstm_scan_kernel(int ysel, const float* __restrict__ Whh)
{
    constexpr int KS = HH + 4;   // 260; KS % 32 == 4 -> conflict-free fragments

    extern __shared__ float sm[];
    float* Wsm = sm;             // [NR][KS]  tf32 weight slab (resident whole scan)
    float* Usm = Wsm + NR * KS;  // [BSUB][KS] h_{t-1} (tf32)

    float* Ydst = (ysel == 0) ? g_Y0 : g_Y1;

    const int cta = blockIdx.x;
    const int bg  = cta / NNC;
    const int nc  = cta % NNC;
    const int rb0 = bg * BSUB;
    const int tid = threadIdx.x;

    // ---- Weight slab (j-major permuted rows), tf32
    for (int idx = tid; idx < NR * HH; idx += NTHREADS) {
        int rl = idx >> 8, k = idx & 255;
        int rw = (rl & 3) * HH + (nc * 8 + (rl >> 2));
        Wsm[rl * KS + k] = to_tf32(Whh[(size_t)rw * HH + k]);
    }
    // ---- Zero Usm (h_{-1} = 0)
    for (int idx = tid * 4; idx < BSUB * HH; idx += NTHREADS * 4) {
        int b = idx >> 8, k = idx & 255;
        *reinterpret_cast<float4*>(&Usm[b * KS + k]) = make_float4(0.f, 0.f, 0.f, 0.f);
    }

    const int lane = tid & 31, wid = tid >> 5;
    const int wm = wid >> 2;            // 0..1 batch half
    const int wn = wid & 3;             // 0..3 n8-tile (2 h-cols x 4 gates)
    const int grp = lane >> 2, tg = lane & 3;

    const uint32_t* Ua = reinterpret_cast<const uint32_t*>(&Usm[(wm * 16 + grp) * KS + tg]);
    const uint32_t* Wb = reinterpret_cast<const uint32_t*>(&Wsm[(wn * 8 + grp) * KS + tg]);

    const int bA   = rb0 + wm * 16 + grp;       // batch row of accumulator rows c0,c1
    const int colP = nc * 32 + wn * 8 + 2 * tg; // permuted gate column of c0
    const float* xgA = g_XG + (size_t)bA * TT * G4H + colP;
    const float* xgB = xgA + (size_t)8 * TT * G4H;   // batch row bA+8 (c2,c3)

    const bool odd = (tg & 1);
    const int bmine = bA + (odd ? 8 : 0);               // (b,j) this lane owns
    const int jg    = nc * 8 + 2 * wn + (tg >> 1);
    float c_state = 0.f;

    unsigned target = 0;

    for (int t = 0; t < TT; ++t) {
        // xg preload (no dependency on h; fully hidden)
        float2 x01 = *reinterpret_cast<const float2*>(xgA);
        float2 x23 = *reinterpret_cast<const float2*>(xgB);
        xgA += G4H; xgB += G4H;
        float c0 = x01.x, c1 = x01.y, c2 = x23.x, c3 = x23.y;

        // Stage h_{t-1} (L2 loads), tf32
        if (t > 0) {
            const float* hsrc = g_h[t & 1];
            for (int idx = tid * 4; idx < BSUB * HH; idx += NTHREADS * 4) {
                int b = idx >> 8, k = idx & 255;
                float4 v = __ldcg(reinterpret_cast<const float4*>(
                    hsrc + (size_t)(rb0 + b) * HH + k));
                v.x = to_tf32(v.x); v.y = to_tf32(v.y);
                v.z = to_tf32(v.z); v.w = to_tf32(v.w);
                *reinterpret_cast<float4*>(&Usm[b * KS + k]) = v;
            }
        }
        __syncthreads();

        // Whh * h_{t-1}: warp m16 x n8, K = 256
#pragma unroll
        for (int kt = 0; kt < HH / 8; ++kt) {
            uint32_t a0 = Ua[kt * 8];
            uint32_t a1 = Ua[8 * KS + kt * 8];
            uint32_t a2 = Ua[kt * 8 + 4];
            uint32_t a3 = Ua[8 * KS + kt * 8 + 4];
            uint32_t b0 = Wb[kt * 8];
            uint32_t b1 = Wb[kt * 8 + 4];
            mma_tf32(c0, c1, c2, c3, a0, a1, a2, a3, b0, b1);
        }

        // Gate exchange within lane pair (tg, tg^1): even lane ends with row bA,
        // odd lane with row bA+8; both get full (i,f,g,o) for their (b, j).
        float s0 = odd ? c0 : c2;
        float s1 = odd ? c1 : c3;
        float r0 = __shfl_xor_sync(0xffffffffu, s0, 1);
        float r1 = __shfl_xor_sync(0xffffffffu, s1, 1);
        float iv = odd ? r0 : c0;
        float fv = odd ? r1 : c1;
        float gv = odd ? c2 : r0;
        float ov = odd ? c3 : r1;

        float is = 1.f / (1.f + expf(-iv));
        float fs = 1.f / (1.f + expf(-fv));
        float gt = tanhf(gv);
        float os = 1.f / (1.f + expf(-ov));
        c_state = fs * c_state + is * gt;
        float hn = os * tanhf(c_state);

        g_h[(t + 1) & 1][bmine * HH + jg] = hn;
        Ydst[((size_t)bmine * TT + t) * HH + jg] = hn;

        // Batch-group barrier
        __threadfence();
        __syncthreads();
        target += NNC;
        if (tid == 0) {
            atomicAdd(&g_ctr[bg], 1u);
            while (atomicAdd(&g_ctr[bg], 0u) < target) { __nanosleep(32); }
            __threadfence();
        }
        __syncthreads();
    }
}

// Final FC: out[b*T + t] = dot(Y0[b,t,:], fc_W) + fc_b. One warp per row.
__global__ void __launch_bounds__(256)
fc_kernel(const float* __restrict__ w, const float* __restrict__ bptr,
          float* __restrict__ out)
{
    int row  = blockIdx.x * 8 + (threadIdx.x >> 5);
    int lane = threadIdx.x & 31;
    const float* yr = g_Y0 + (size_t)row * HH;
    float4 a0 = *reinterpret_cast<const float4*>(yr + lane * 4);
    float4 a1 = *reinterpret_cast<const float4*>(yr + 128 + lane * 4);
    float4 w0 = *reinterpret_cast<const float4*>(w + lane * 4);
    float4 w1 = *reinterpret_cast<const float4*>(w + 128 + lane * 4);
    float s = a0.x * w0.x + a0.y * w0.y + a0.z * w0.z + a0.w * w0.w
            + a1.x * w1.x + a1.y * w1.y + a1.z * w1.z + a1.w * w1.w;
#pragma unroll
    for (int off = 16; off > 0; off >>= 1)
        s += __shfl_xor_sync(0xffffffffu, s, off);
    if (lane == 0) out[row] = s + bptr[0];
}

extern "C" void kernel_launch(void* const* d_in, const int* in_sizes, int n_in,
                              void* d_out, int out_size)
{
    const float* x        = (const float*)d_in[0];
    const float* Wih0     = (const float*)d_in[1];
    const float* Whh0     = (const float*)d_in[2];
    const float* Wih_rest = (const float*)d_in[3];
    const float* Whh_rest = (const float*)d_in[4];
    const float* bih      = (const float*)d_in[5];
    const float* bhh      = (const float*)d_in[6];
    const float* fcW      = (const float*)d_in[7];
    const float* fcb      = (const float*)d_in[8];
    float* out = (float*)d_out;

    size_t gsmem0 = (size_t)(128 * (DD + 4) + 64 * (DD + 4) + 64) * sizeof(float);  // ~100 KB
    size_t gsmem1 = (size_t)(128 * (HH + 4) + 64 * (HH + 4) + 64) * sizeof(float);  // ~195 KB
    size_t ssmem  = (size_t)(NR * (HH + 4) + BSUB * (HH + 4)) * sizeof(float);      // ~65 KB

    cudaFuncSetAttribute(xg_gemm_kernel<DD>,
                         cudaFuncAttributeMaxDynamicSharedMemorySize, (int)gsmem0);
    cudaFuncSetAttribute(xg_gemm_kernel<HH>,
                         cudaFuncAttributeMaxDynamicSharedMemorySize, (int)gsmem1);
    cudaFuncSetAttribute(lstm_scan_kernel,
                         cudaFuncAttributeMaxDynamicSharedMemorySize, (int)ssmem);

    dim3 ggrid(G4H / 64, (BB * TT) / 128);   // 16 x 1024
    dim3 sgrid(NBG * NNC);                   // 128

    for (int l = 0; l < 5; ++l) {
        const float* bi = bih + (size_t)l * G4H;
        const float* bh = bhh + (size_t)l * G4H;
        if (l == 0) {
            xg_gemm_kernel<DD><<<ggrid, 256, gsmem0>>>(x, 0, Wih0, bi, bh);
        } else {
            int xsel = ((l - 1) & 1) == 0 ? 1 : 2;   // read Y0 for l=1,3 ; Y1 for l=2,4
            const float* Wih = Wih_rest + (size_t)(l - 1) * G4H * HH;
            xg_gemm_kernel<HH><<<ggrid, 256, gsmem1>>>(nullptr, xsel, Wih, bi, bh);
        }
        const float* Whh = (l == 0) ? Whh0 : (Whh_rest + (size_t)(l - 1) * G4H * HH);
        reset_kernel<<<1, 32>>>();
        lstm_scan_kernel<<<sgrid, NTHREADS, ssmem>>>(/*ysel=*/l & 1, Whh);
    }

    // Final layer (l=4) wrote Y0. FC head: [B*T] rows, one warp each.
    fc_kernel<<<(BB * TT) / 8, 256>>>(fcW, fcb, out);
}

// round 6
// speedup vs baseline: 2.8863x; 1.1433x over previous
#include <cuda_runtime.h>
#include <stdint.h>
#include <math.h>

// Problem constants
#define BB   128
#define TT   1024
#define DD   128
#define HH   256
#define G4H  1024

// Scan decomposition: 8 batch-groups x 16 N-slice CTAs = 128 CTAs
#define NBG  8
#define NNC  16
#define BSUB 16          // batch rows per CTA  (128/8)
#define HC   16          // h columns per CTA   (256/16)
#define NR   64          // gate cols per CTA (j-major: p = j_local*4 + gate)
#define NTHREADS 256
#define KS   264         // padded smem row stride (words); KS % 32 == 8

// Device scratch (static — no allocation allowed)
__device__ float    g_XG[(size_t)BB * TT * G4H]; // 512 MB precomputed input gates (+bias)
__device__ float    g_Y0[(size_t)BB * TT * HH];  // 128 MB ping
__device__ float    g_Y1[(size_t)BB * TT * HH];  // 128 MB pong
__device__ float    g_h[2][BB * HH];             // h double buffer (parity = step index)
__device__ unsigned g_ctr[NBG];                  // per-batch-group barrier counters

__global__ void reset_kernel() {
    if (threadIdx.x < NBG) g_ctr[threadIdx.x] = 0u;
}

__device__ __forceinline__ float to_tf32(float x) {
    float r;
    asm("cvt.rna.tf32.f32 %0, %1;" : "=f"(r) : "f"(x));
    return r;
}

__device__ __forceinline__ void mma_tf32(float& c0, float& c1, float& c2, float& c3,
                                         uint32_t a0, uint32_t a1, uint32_t a2, uint32_t a3,
                                         uint32_t b0, uint32_t b1) {
    asm volatile(
        "mma.sync.aligned.m16n8k8.row.col.f32.tf32.tf32.f32 "
        "{%0,%1,%2,%3}, {%4,%5,%6,%7}, {%8,%9}, {%0,%1,%2,%3};\n"
        : "+f"(c0), "+f"(c1), "+f"(c2), "+f"(c3)
        : "r"(a0), "r"(a1), "r"(a2), "r"(a3), "r"(b0), "r"(b1));
}

__device__ __forceinline__ void red_release_add(unsigned* p) {
    asm volatile("red.release.gpu.global.add.u32 [%0], 1;" :: "l"(p) : "memory");
}
__device__ __forceinline__ unsigned ld_acquire(unsigned* p) {
    unsigned v;
    asm volatile("ld.acquire.gpu.global.u32 %0, [%1];" : "=r"(v) : "l"(p) : "memory");
    return v;
}

// pair-interleaved slot within an 8-block: logical k -> slot ((k&3)*2) | ((k>>2)&1)
__device__ __forceinline__ int kslot(int k) {
    return (k & ~7) + (((k & 3) << 1) | ((k >> 2) & 1));
}

// ============================================================================
// xg GEMM: g_XG[m, P] = sum_k In[m,k] * Wih[perm(P), k] + bih[perm(P)] + bhh[...]
// P is j-major permuted: P = j_global*4 + gate; perm(P) = (P&3)*HH + (P>>2).
// CTA tile 128(m) x 64(n), full K in smem. 8 warps = 4(m) x 2(n), warp m32n32.
// ============================================================================
template <int K>
__global__ void __launch_bounds__(256, 1)
xg_gemm_kernel(const float* __restrict__ xext, int xsel,
               const float* __restrict__ Wih,
               const float* __restrict__ bih, const float* __restrict__ bhh)
{
    constexpr int KSg = K + 4;                // padded stride; KSg % 32 == 4
    extern __shared__ float sm[];
    float* As   = sm;                         // [128][KSg]
    float* Bs   = As + 128 * KSg;             // [64][KSg]
    float* bias = Bs + 64 * KSg;              // [64]

    const float* In = (xsel == 0) ? xext : ((xsel == 1) ? g_Y0 : g_Y1);
    const int m0  = blockIdx.y * 128;
    const int n0  = blockIdx.x * 64;
    const int tid = threadIdx.x;

    for (int idx = tid; idx < 128 * (K / 4); idx += 256) {
        int r = idx / (K / 4), k4 = idx - r * (K / 4);
        float4 v = *reinterpret_cast<const float4*>(In + (size_t)(m0 + r) * K + k4 * 4);
        v.x = to_tf32(v.x); v.y = to_tf32(v.y); v.z = to_tf32(v.z); v.w = to_tf32(v.w);
        *reinterpret_cast<float4*>(&As[r * KSg + k4 * 4]) = v;
    }
    for (int idx = tid; idx < 64 * (K / 4); idx += 256) {
        int n = idx / (K / 4), k4 = idx - n * (K / 4);
        int P  = n0 + n;
        int rw = (P & 3) * HH + (P >> 2);
        float4 v = *reinterpret_cast<const float4*>(Wih + (size_t)rw * K + k4 * 4);
        v.x = to_tf32(v.x); v.y = to_tf32(v.y); v.z = to_tf32(v.z); v.w = to_tf32(v.w);
        *reinterpret_cast<float4*>(&Bs[n * KSg + k4 * 4]) = v;
    }
    if (tid < 64) {
        int P  = n0 + tid;
        int bx = (P & 3) * HH + (P >> 2);
        bias[tid] = bih[bx] + bhh[bx];
    }
    __syncthreads();

    const int lane = tid & 31, wid = tid >> 5;
    const int wm = wid >> 1, wn = wid & 1;
    const int grp = lane >> 2, tg = lane & 3;

    float acc[2][4][4];
#pragma unroll
    for (int mi = 0; mi < 2; ++mi)
#pragma unroll
        for (int ni = 0; ni < 4; ++ni)
#pragma unroll
            for (int q = 0; q < 4; ++q) acc[mi][ni][q] = 0.f;

    const uint32_t* Ap0 = reinterpret_cast<const uint32_t*>(&As[(wm * 32 + grp) * KSg + tg]);
    const uint32_t* Bp0 = reinterpret_cast<const uint32_t*>(&Bs[(wn * 32 + grp) * KSg + tg]);

#pragma unroll 4
    for (int kt = 0; kt < K / 8; ++kt) {
        uint32_t a[2][4], bf[4][2];
#pragma unroll
        for (int mi = 0; mi < 2; ++mi) {
            const uint32_t* p = Ap0 + mi * 16 * KSg + kt * 8;
            a[mi][0] = p[0]; a[mi][1] = p[8 * KSg]; a[mi][2] = p[4]; a[mi][3] = p[8 * KSg + 4];
        }
#pragma unroll
        for (int ni = 0; ni < 4; ++ni) {
            const uint32_t* p = Bp0 + ni * 8 * KSg + kt * 8;
            bf[ni][0] = p[0]; bf[ni][1] = p[4];
        }
#pragma unroll
        for (int mi = 0; mi < 2; ++mi)
#pragma unroll
            for (int ni = 0; ni < 4; ++ni)
                mma_tf32(acc[mi][ni][0], acc[mi][ni][1], acc[mi][ni][2], acc[mi][ni][3],
                         a[mi][0], a[mi][1], a[mi][2], a[mi][3], bf[ni][0], bf[ni][1]);
    }

#pragma unroll
    for (int mi = 0; mi < 2; ++mi)
#pragma unroll
        for (int ni = 0; ni < 4; ++ni) {
            int rl = wm * 32 + mi * 16 + grp;
            int cl = wn * 32 + ni * 8 + 2 * tg;
            float b0 = bias[cl], b1 = bias[cl + 1];
            size_t o = (size_t)(m0 + rl) * G4H + (n0 + cl);
            *reinterpret_cast<float2*>(&g_XG[o]) =
                make_float2(acc[mi][ni][0] + b0, acc[mi][ni][1] + b1);
            *reinterpret_cast<float2*>(&g_XG[o + (size_t)8 * G4H]) =
                make_float2(acc[mi][ni][2] + b0, acc[mi][ni][3] + b1);
        }
}

// ============================================================================
// LSTM scan: per step Whh*h via tensor cores (xg preloaded into accumulators).
// 8 warps, each m16 x n8 (2 h-cols x 4 gates), K = 256 in 4 independent chains.
// Pair-interleaved smem layout -> all fragment loads are conflict-free LDS.64.
// ============================================================================
__global__ void __launch_bounds__(NTHREADS, 1)
lstm_scan_kernel(int ysel, const float* __restrict__ Whh)
{
    extern __shared__ float sm[];
    float* Wsm = sm;              // [NR][KS]   tf32 weight slab (resident whole scan)
    float* Usm = Wsm + NR * KS;   // [BSUB][KS] h_{t-1} (tf32, pair-interleaved)
    float* Hs  = Usm + BSUB * KS; // [BSUB*HC]  h bounce for coalesced stores

    float* Ydst = (ysel == 0) ? g_Y0 : g_Y1;

    const int cta = blockIdx.x;
    const int bg  = cta / NNC;
    const int nc  = cta % NNC;
    const int rb0 = bg * BSUB;
    const int tid = threadIdx.x;
    unsigned* ctr = &g_ctr[bg];

    // ---- Weight slab (j-major permuted rows, pair-interleaved k), tf32
    for (int idx = tid; idx < NR * HH; idx += NTHREADS) {
        int rl = idx >> 8, k = idx & 255;
        int rw = (rl & 3) * HH + (nc * HC + (rl >> 2));
        Wsm[rl * KS + kslot(k)] = to_tf32(Whh[(size_t)rw * HH + k]);
    }
    // ---- Zero Usm (h_{-1} = 0)
    for (int idx = tid * 4; idx < BSUB * KS; idx += NTHREADS * 4)
        *reinterpret_cast<float4*>(&Usm[idx]) = make_float4(0.f, 0.f, 0.f, 0.f);

    const int lane = tid & 31, wid = tid >> 5;     // wid = n8-tile index (0..7)
    const int grp = lane >> 2, tg = lane & 3;

    const uint32_t* Ua0 = reinterpret_cast<const uint32_t*>(&Usm[grp * KS + 2 * tg]);
    const uint32_t* Ua1 = Ua0 + 8 * KS;
    const uint32_t* Wb  = reinterpret_cast<const uint32_t*>(&Wsm[(wid * 8 + grp) * KS + 2 * tg]);

    const int bA   = rb0 + grp;                    // batch row of accum rows c0,c1
    const int colP = nc * NR + wid * 8 + 2 * tg;   // permuted gate column of c0
    const float* xgA = g_XG + (size_t)bA * TT * G4H + colP;
    const float* xgB = xgA + (size_t)8 * TT * G4H; // batch row bA+8 (c2,c3)

    const bool odd  = (tg & 1);
    const int bl    = grp + (odd ? 8 : 0);         // local batch row this lane owns
    const int jl    = 2 * wid + (tg >> 1);         // local h-col this lane owns

    // coalesced-store mapping: thread i -> (b = i>>4, j = i&15)
    const int sb = tid >> 4, sj = tid & 15;
    float* hout0 = &g_h[0][(rb0 + sb) * HH + nc * HC + sj];
    float* hout1 = &g_h[1][(rb0 + sb) * HH + nc * HC + sj];
    float* yout  = &Ydst[((size_t)(rb0 + sb) * TT) * HH + nc * HC + sj];

    // staging mapping: thread -> row (tid>>4), 2 k8-blocks starting at (tid&15)*2
    const int strow = tid >> 4;
    const int stkb  = (tid & 15) * 2;

    float c_state = 0.f;
    unsigned target = 0;

    for (int t = 0; t < TT; ++t) {
        // xg preload (independent of h)
        float2 x01 = *reinterpret_cast<const float2*>(xgA);
        float2 x23 = *reinterpret_cast<const float2*>(xgB);
        xgA += G4H; xgB += G4H;

        // ---- Stage h_{t-1} -> Usm (pair-interleaved), L2 loads
        if (t > 0) {
            const float* hrow = g_h[t & 1] + (size_t)(rb0 + strow) * HH;
            float* urow = &Usm[strow * KS];
#pragma unroll
            for (int q = 0; q < 2; ++q) {
                int kb = (stkb + q) * 8;
                float4 lo = __ldcg(reinterpret_cast<const float4*>(hrow + kb));
                float4 hi = __ldcg(reinterpret_cast<const float4*>(hrow + kb + 4));
                float* up = urow + kb;
                *reinterpret_cast<float2*>(up + 0) = make_float2(to_tf32(lo.x), to_tf32(hi.x));
                *reinterpret_cast<float2*>(up + 2) = make_float2(to_tf32(lo.y), to_tf32(hi.y));
                *reinterpret_cast<float2*>(up + 4) = make_float2(to_tf32(lo.z), to_tf32(hi.z));
                *reinterpret_cast<float2*>(up + 6) = make_float2(to_tf32(lo.w), to_tf32(hi.w));
            }
        }
        __syncthreads();   // Usm ready (also covers init at t=0)

        // ---- Whh * h_{t-1}: m16 x n8, K=256 as 4 independent chains
        float a0c[4], a1c[4], a2c[4], a3c[4];
        a0c[0] = x01.x; a1c[0] = x01.y; a2c[0] = x23.x; a3c[0] = x23.y;
#pragma unroll
        for (int c = 1; c < 4; ++c) { a0c[c] = 0.f; a1c[c] = 0.f; a2c[c] = 0.f; a3c[c] = 0.f; }

#pragma unroll
        for (int kk = 0; kk < 8; ++kk) {
#pragma unroll
            for (int c = 0; c < 4; ++c) {
                int off = (c * 8 + kk) * 8;
                uint2 u0 = *reinterpret_cast<const uint2*>(Ua0 + off);
                uint2 u1 = *reinterpret_cast<const uint2*>(Ua1 + off);
                uint2 wv = *reinterpret_cast<const uint2*>(Wb  + off);
                mma_tf32(a0c[c], a1c[c], a2c[c], a3c[c],
                         u0.x, u1.x, u0.y, u1.y, wv.x, wv.y);
            }
        }
        float c0 = (a0c[0] + a0c[1]) + (a0c[2] + a0c[3]);
        float c1 = (a1c[0] + a1c[1]) + (a1c[2] + a1c[3]);
        float c2 = (a2c[0] + a2c[1]) + (a2c[2] + a2c[3]);
        float c3 = (a3c[0] + a3c[1]) + (a3c[2] + a3c[3]);

        // ---- Gate exchange within lane pair (tg, tg^1)
        float s0 = odd ? c0 : c2;
        float s1 = odd ? c1 : c3;
        float r0 = __shfl_xor_sync(0xffffffffu, s0, 1);
        float r1 = __shfl_xor_sync(0xffffffffu, s1, 1);
        float iv = odd ? r0 : c0;
        float fv = odd ? r1 : c1;
        float gv = odd ? c2 : r0;
        float ov = odd ? c3 : r1;

        float is = 1.f / (1.f + __expf(-iv));
        float fs = 1.f / (1.f + __expf(-fv));
        float gt = tanhf(gv);
        float os = 1.f / (1.f + __expf(-ov));
        c_state = fs * c_state + is * gt;
        float hn = os * tanhf(c_state);

        Hs[bl * HC + jl] = hn;
        __syncthreads();   // Hs complete

        // ---- Coalesced h store (64B row segments)
        float hv = Hs[sb * HC + sj];
        if (t & 1) hout0[0] = hv; else hout1[0] = hv;   // write g_h[(t+1)&1]
        __syncthreads();   // h stores happen-before release

        if (tid == 0) red_release_add(ctr);

        // ---- Y store overlaps the barrier wait
        yout[(size_t)t * HH] = hv;

        target += NNC;
        if (tid == 0) {
            while (ld_acquire(ctr) < target) { }
        }
        __syncthreads();   // all threads past the barrier
    }
}

// Final FC: out[b*T + t] = dot(Y0[b,t,:], fc_W) + fc_b. One warp per row.
__global__ void __launch_bounds__(256)
fc_kernel(const float* __restrict__ w, const float* __restrict__ bptr,
          float* __restrict__ out)
{
    int row  = blockIdx.x * 8 + (threadIdx.x >> 5);
    int lane = threadIdx.x & 31;
    const float* yr = g_Y0 + (size_t)row * HH;
    float4 a0 = *reinterpret_cast<const float4*>(yr + lane * 4);
    float4 a1 = *reinterpret_cast<const float4*>(yr + 128 + lane * 4);
    float4 w0 = *reinterpret_cast<const float4*>(w + lane * 4);
    float4 w1 = *reinterpret_cast<const float4*>(w + 128 + lane * 4);
    float s = a0.x * w0.x + a0.y * w0.y + a0.z * w0.z + a0.w * w0.w
            + a1.x * w1.x + a1.y * w1.y + a1.z * w1.z + a1.w * w1.w;
#pragma unroll
    for (int off = 16; off > 0; off >>= 1)
        s += __shfl_xor_sync(0xffffffffu, s, off);
    if (lane == 0) out[row] = s + bptr[0];
}

extern "C" void kernel_launch(void* const* d_in, const int* in_sizes, int n_in,
                              void* d_out, int out_size)
{
    const float* x        = (const float*)d_in[0];
    const float* Wih0     = (const float*)d_in[1];
    const float* Whh0     = (const float*)d_in[2];
    const float* Wih_rest = (const float*)d_in[3];
    const float* Whh_rest = (const float*)d_in[4];
    const float* bih      = (const float*)d_in[5];
    const float* bhh      = (const float*)d_in[6];
    const float* fcW      = (const float*)d_in[7];
    const float* fcb      = (const float*)d_in[8];
    float* out = (float*)d_out;

    size_t gsmem0 = (size_t)(128 * (DD + 4) + 64 * (DD + 4) + 64) * sizeof(float);
    size_t gsmem1 = (size_t)(128 * (HH + 4) + 64 * (HH + 4) + 64) * sizeof(float);
    size_t ssmem  = (size_t)(NR * KS + BSUB * KS + BSUB * HC) * sizeof(float);   // ~85.5 KB

    cudaFuncSetAttribute(xg_gemm_kernel<DD>,
                         cudaFuncAttributeMaxDynamicSharedMemorySize, (int)gsmem0);
    cudaFuncSetAttribute(xg_gemm_kernel<HH>,
                         cudaFuncAttributeMaxDynamicSharedMemorySize, (int)gsmem1);
    cudaFuncSetAttribute(lstm_scan_kernel,
                         cudaFuncAttributeMaxDynamicSharedMemorySize, (int)ssmem);

    dim3 ggrid(G4H / 64, (BB * TT) / 128);   // 16 x 1024
    dim3 sgrid(NBG * NNC);                   // 128

    for (int l = 0; l < 5; ++l) {
        const float* bi = bih + (size_t)l * G4H;
        const float* bh = bhh + (size_t)l * G4H;
        if (l == 0) {
            xg_gemm_kernel<DD><<<ggrid, 256, gsmem0>>>(x, 0, Wih0, bi, bh);
        } else {
            int xsel = ((l - 1) & 1) == 0 ? 1 : 2;   // read Y0 for l=1,3 ; Y1 for l=2,4
            const float* Wih = Wih_rest + (size_t)(l - 1) * G4H * HH;
            xg_gemm_kernel<HH><<<ggrid, 256, gsmem1>>>(nullptr, xsel, Wih, bi, bh);
        }
        const float* Whh = (l == 0) ? Whh0 : (Whh_rest + (size_t)(l - 1) * G4H * HH);
        reset_kernel<<<1, 32>>>();
        lstm_scan_kernel<<<sgrid, NTHREADS, ssmem>>>(/*ysel=*/l & 1, Whh);
    }

    // Final layer (l=4) wrote Y0. FC head: [B*T] rows, one warp each.
    fc_kernel<<<(BB * TT) / 8, 256>>>(fcW, fcb, out);
}

// round 7
// speedup vs baseline: 2.9772x; 1.0315x over previous
#include <cuda_runtime.h>
#include <stdint.h>
#include <math.h>

// Problem constants
#define BB   128
#define TT   1024
#define DD   128
#define HH   256
#define G4H  1024

// Scan decomposition: 8 batch-groups x 16 N-slice CTAs = 128 CTAs
#define NBG  8
#define NNC  16
#define BSUB 16          // batch rows per CTA  (128/8)
#define HC   16          // h columns per CTA   (256/16)
#define NR   64          // gate cols per CTA (j-major: p = j_local*4 + gate)
#define NTHREADS 256
#define KS   264         // padded smem row stride (words); KS % 32 == 8

// Device scratch (static — no allocation allowed)
__device__ float    g_XG[(size_t)BB * TT * G4H]; // 512 MB precomputed input gates (+bias)
__device__ float    g_Y0[(size_t)BB * TT * HH];  // 128 MB ping
__device__ float    g_Y1[(size_t)BB * TT * HH];  // 128 MB pong
__device__ float    g_h[2][BB * HH];             // h (tf32, pair-interleaved), dbl buffer
__device__ unsigned g_ctr[NBG];                  // per-batch-group barrier counters

__global__ void reset_kernel() {
    if (threadIdx.x < NBG) g_ctr[threadIdx.x] = 0u;
}

__device__ __forceinline__ float to_tf32(float x) {
    float r;
    asm("cvt.rna.tf32.f32 %0, %1;" : "=f"(r) : "f"(x));
    return r;
}

__device__ __forceinline__ float sigf(float x) {
    return 1.f / (1.f + __expf(-x));
}
__device__ __forceinline__ float tanh_fast(float x) {
    return 2.f / (1.f + __expf(-2.f * x)) - 1.f;
}

__device__ __forceinline__ void mma_tf32(float& c0, float& c1, float& c2, float& c3,
                                         uint32_t a0, uint32_t a1, uint32_t a2, uint32_t a3,
                                         uint32_t b0, uint32_t b1) {
    asm volatile(
        "mma.sync.aligned.m16n8k8.row.col.f32.tf32.tf32.f32 "
        "{%0,%1,%2,%3}, {%4,%5,%6,%7}, {%8,%9}, {%0,%1,%2,%3};\n"
        : "+f"(c0), "+f"(c1), "+f"(c2), "+f"(c3)
        : "r"(a0), "r"(a1), "r"(a2), "r"(a3), "r"(b0), "r"(b1));
}

__device__ __forceinline__ void red_release_add(unsigned* p) {
    asm volatile("red.release.gpu.global.add.u32 [%0], 1;" :: "l"(p) : "memory");
}
__device__ __forceinline__ unsigned ld_acquire(unsigned* p) {
    unsigned v;
    asm volatile("ld.acquire.gpu.global.u32 %0, [%1];" : "=r"(v) : "l"(p) : "memory");
    return v;
}

// pair-interleaved slot within an 8-block: logical k -> slot ((k&3)*2) | ((k>>2)&1)
__device__ __forceinline__ int kslot(int k) {
    return (k & ~7) + (((k & 3) << 1) | ((k >> 2) & 1));
}

// ============================================================================
// xg GEMM: g_XG[m, P] = sum_k In[m,k] * Wih[perm(P), k] + bih[perm(P)] + bhh[...]
// P is j-major permuted: P = j_global*4 + gate; perm(P) = (P&3)*HH + (P>>2).
// CTA tile 128(m) x 64(n), full K in smem. 8 warps = 4(m) x 2(n), warp m32n32.
// ============================================================================
template <int K>
__global__ void __launch_bounds__(256, 1)
xg_gemm_kernel(const float* __restrict__ xext, int xsel,
               const float* __restrict__ Wih,
               const float* __restrict__ bih, const float* __restrict__ bhh)
{
    constexpr int KSg = K + 4;                // padded stride; KSg % 32 == 4
    extern __shared__ float sm[];
    float* As   = sm;                         // [128][KSg]
    float* Bs   = As + 128 * KSg;             // [64][KSg]
    float* bias = Bs + 64 * KSg;              // [64]

    const float* In = (xsel == 0) ? xext : ((xsel == 1) ? g_Y0 : g_Y1);
    const int m0  = blockIdx.y * 128;
    const int n0  = blockIdx.x * 64;
    const int tid = threadIdx.x;

    for (int idx = tid; idx < 128 * (K / 4); idx += 256) {
        int r = idx / (K / 4), k4 = idx - r * (K / 4);
        float4 v = *reinterpret_cast<const float4*>(In + (size_t)(m0 + r) * K + k4 * 4);
        v.x = to_tf32(v.x); v.y = to_tf32(v.y); v.z = to_tf32(v.z); v.w = to_tf32(v.w);
        *reinterpret_cast<float4*>(&As[r * KSg + k4 * 4]) = v;
    }
    for (int idx = tid; idx < 64 * (K / 4); idx += 256) {
        int n = idx / (K / 4), k4 = idx - n * (K / 4);
        int P  = n0 + n;
        int rw = (P & 3) * HH + (P >> 2);
        float4 v = *reinterpret_cast<const float4*>(Wih + (size_t)rw * K + k4 * 4);
        v.x = to_tf32(v.x); v.y = to_tf32(v.y); v.z = to_tf32(v.z); v.w = to_tf32(v.w);
        *reinterpret_cast<float4*>(&Bs[n * KSg + k4 * 4]) = v;
    }
    if (tid < 64) {
        int P  = n0 + tid;
        int bx = (P & 3) * HH + (P >> 2);
        bias[tid] = bih[bx] + bhh[bx];
    }
    __syncthreads();

    const int lane = tid & 31, wid = tid >> 5;
    const int wm = wid >> 1, wn = wid & 1;
    const int grp = lane >> 2, tg = lane & 3;

    float acc[2][4][4];
#pragma unroll
    for (int mi = 0; mi < 2; ++mi)
#pragma unroll
        for (int ni = 0; ni < 4; ++ni)
#pragma unroll
            for (int q = 0; q < 4; ++q) acc[mi][ni][q] = 0.f;

    const uint32_t* Ap0 = reinterpret_cast<const uint32_t*>(&As[(wm * 32 + grp) * KSg + tg]);
    const uint32_t* Bp0 = reinterpret_cast<const uint32_t*>(&Bs[(wn * 32 + grp) * KSg + tg]);

#pragma unroll 4
    for (int kt = 0; kt < K / 8; ++kt) {
        uint32_t a[2][4], bf[4][2];
#pragma unroll
        for (int mi = 0; mi < 2; ++mi) {
            const uint32_t* p = Ap0 + mi * 16 * KSg + kt * 8;
            a[mi][0] = p[0]; a[mi][1] = p[8 * KSg]; a[mi][2] = p[4]; a[mi][3] = p[8 * KSg + 4];
        }
#pragma unroll
        for (int ni = 0; ni < 4; ++ni) {
            const uint32_t* p = Bp0 + ni * 8 * KSg + kt * 8;
            bf[ni][0] = p[0]; bf[ni][1] = p[4];
        }
#pragma unroll
        for (int mi = 0; mi < 2; ++mi)
#pragma unroll
            for (int ni = 0; ni < 4; ++ni)
                mma_tf32(acc[mi][ni][0], acc[mi][ni][1], acc[mi][ni][2], acc[mi][ni][3],
                         a[mi][0], a[mi][1], a[mi][2], a[mi][3], bf[ni][0], bf[ni][1]);
    }

#pragma unroll
    for (int mi = 0; mi < 2; ++mi)
#pragma unroll
        for (int ni = 0; ni < 4; ++ni) {
            int rl = wm * 32 + mi * 16 + grp;
            int cl = wn * 32 + ni * 8 + 2 * tg;
            float b0 = bias[cl], b1 = bias[cl + 1];
            size_t o = (size_t)(m0 + rl) * G4H + (n0 + cl);
            *reinterpret_cast<float2*>(&g_XG[o]) =
                make_float2(acc[mi][ni][0] + b0, acc[mi][ni][1] + b1);
            *reinterpret_cast<float2*>(&g_XG[o + (size_t)8 * G4H]) =
                make_float2(acc[mi][ni][2] + b0, acc[mi][ni][3] + b1);
        }
}

// ============================================================================
// LSTM scan: per step Whh*h via tensor cores (xg preloaded into accumulators).
// W fragments live in REGISTERS (scan-invariant). g_h holds tf32-rounded,
// pair-interleaved rows so consumer staging is a verbatim float4 copy.
// ============================================================================
__global__ void __launch_bounds__(NTHREADS, 1)
lstm_scan_kernel(int ysel, const float* __restrict__ Whh)
{
    extern __shared__ float sm[];
    float* Wsm = sm;              // [NR][KS]   tf32 weight slab (staging for reg load)
    float* Usm = Wsm + NR * KS;   // [BSUB][KS] h_{t-1} (tf32, pair-interleaved)
    float* Hs  = Usm + BSUB * KS; // [BSUB*HC]  tf32-interleaved h bounce
    float* Hs2 = Hs + BSUB * HC;  // [BSUB*HC]  fp32 plain h bounce (for Y)

    float* Ydst = (ysel == 0) ? g_Y0 : g_Y1;

    const int cta = blockIdx.x;
    const int bg  = cta / NNC;
    const int nc  = cta % NNC;
    const int rb0 = bg * BSUB;
    const int tid = threadIdx.x;
    unsigned* ctr = &g_ctr[bg];

    // ---- Weight slab (j-major permuted rows, pair-interleaved k), tf32
    for (int idx = tid; idx < NR * HH; idx += NTHREADS) {
        int rl = idx >> 8, k = idx & 255;
        int rw = (rl & 3) * HH + (nc * HC + (rl >> 2));
        Wsm[rl * KS + kslot(k)] = to_tf32(Whh[(size_t)rw * HH + k]);
    }
    // ---- Zero Usm (h_{-1} = 0)
    for (int idx = tid * 4; idx < BSUB * KS; idx += NTHREADS * 4)
        *reinterpret_cast<float4*>(&Usm[idx]) = make_float4(0.f, 0.f, 0.f, 0.f);
    __syncthreads();

    const int lane = tid & 31, wid = tid >> 5;     // wid = n8-tile index (0..7)
    const int grp = lane >> 2, tg = lane & 3;

    const uint32_t* Ua0 = reinterpret_cast<const uint32_t*>(&Usm[grp * KS + 2 * tg]);
    const uint32_t* Ua1 = Ua0 + 8 * KS;
    const uint32_t* Wb  = reinterpret_cast<const uint32_t*>(&Wsm[(wid * 8 + grp) * KS + 2 * tg]);

    // ---- Hoist W fragments into registers (32 k-blocks x uint2)
    uint2 wreg[32];
#pragma unroll
    for (int ib = 0; ib < 32; ++ib)
        wreg[ib] = *reinterpret_cast<const uint2*>(Wb + ib * 8);

    const int bA   = rb0 + grp;                    // batch row of accum rows c0,c1
    const int colP = nc * NR + wid * 8 + 2 * tg;   // permuted gate column of c0
    const float* xgA = g_XG + (size_t)bA * TT * G4H + colP;
    const float* xgB = xgA + (size_t)8 * TT * G4H; // batch row bA+8 (c2,c3)

    const bool odd  = (tg & 1);
    const int bl    = grp + (odd ? 8 : 0);         // local batch row this lane owns
    const int jl    = 2 * wid + (tg >> 1);         // local h-col this lane owns
    const int jslot = (jl & ~7) + (((jl & 3) << 1) | ((jl >> 2) & 1)); // interleaved slot

    // coalesced-store mapping: thread i -> (b = i>>4, col-slot = i&15)
    const int sb = tid >> 4, sj = tid & 15;
    float* hout0 = &g_h[0][(rb0 + sb) * HH + nc * HC + sj];
    float* hout1 = &g_h[1][(rb0 + sb) * HH + nc * HC + sj];
    float* yout  = &Ydst[((size_t)(rb0 + sb) * TT) * HH + nc * HC + sj];

    // staging mapping: thread -> row (tid>>4), 16 cols starting at (tid&15)*16
    const int strow = tid >> 4;
    const int stk0  = (tid & 15) * 16;

    float c_state = 0.f;
    unsigned target = 0;

    for (int t = 0; t < TT; ++t) {
        // xg preload (independent of h)
        float2 x01 = *reinterpret_cast<const float2*>(xgA);
        float2 x23 = *reinterpret_cast<const float2*>(xgB);
        xgA += G4H; xgB += G4H;

        // ---- Stage h_{t-1} -> Usm : verbatim float4 copy (already tf32+interleaved)
        if (t > 0) {
            const float* hrow = g_h[t & 1] + (size_t)(rb0 + strow) * HH + stk0;
            float* urow = &Usm[strow * KS + stk0];
#pragma unroll
            for (int q = 0; q < 4; ++q) {
                float4 v = __ldcg(reinterpret_cast<const float4*>(hrow + q * 4));
                *reinterpret_cast<float4*>(urow + q * 4) = v;
            }
        }
        __syncthreads();   // Usm ready (also covers init at t=0)

        // ---- Whh * h_{t-1}: m16 x n8, K=256 as 4 independent chains, W in regs
        float a0c[4], a1c[4], a2c[4], a3c[4];
        a0c[0] = x01.x; a1c[0] = x01.y; a2c[0] = x23.x; a3c[0] = x23.y;
#pragma unroll
        for (int c = 1; c < 4; ++c) { a0c[c] = 0.f; a1c[c] = 0.f; a2c[c] = 0.f; a3c[c] = 0.f; }

#pragma unroll
        for (int kk = 0; kk < 8; ++kk) {
#pragma unroll
            for (int c = 0; c < 4; ++c) {
                int ib = c * 8 + kk;
                uint2 u0 = *reinterpret_cast<const uint2*>(Ua0 + ib * 8);
                uint2 u1 = *reinterpret_cast<const uint2*>(Ua1 + ib * 8);
                mma_tf32(a0c[c], a1c[c], a2c[c], a3c[c],
                         u0.x, u1.x, u0.y, u1.y, wreg[ib].x, wreg[ib].y);
            }
        }
        float c0 = (a0c[0] + a0c[1]) + (a0c[2] + a0c[3]);
        float c1 = (a1c[0] + a1c[1]) + (a1c[2] + a1c[3]);
        float c2 = (a2c[0] + a2c[1]) + (a2c[2] + a2c[3]);
        float c3 = (a3c[0] + a3c[1]) + (a3c[2] + a3c[3]);

        // ---- Gate exchange within lane pair (tg, tg^1)
        float s0 = odd ? c0 : c2;
        float s1 = odd ? c1 : c3;
        float r0 = __shfl_xor_sync(0xffffffffu, s0, 1);
        float r1 = __shfl_xor_sync(0xffffffffu, s1, 1);
        float iv = odd ? r0 : c0;
        float fv = odd ? r1 : c1;
        float gv = odd ? c2 : r0;
        float ov = odd ? c3 : r1;

        float is = sigf(iv);
        float fs = sigf(fv);
        float gt = tanh_fast(gv);
        float os = sigf(ov);
        c_state = fs * c_state + is * gt;
        float hn = os * tanh_fast(c_state);

        Hs [bl * HC + jslot] = to_tf32(hn);   // interleaved tf32 (for recurrence)
        Hs2[bl * HC + jl]    = hn;            // plain fp32 (for Y)
        __syncthreads();   // bounces complete

        // ---- Coalesced h store (64B row segments, pre-interleaved tf32)
        float hv = Hs [sb * HC + sj];
        float yv = Hs2[sb * HC + sj];
        if (t & 1) hout0[0] = hv; else hout1[0] = hv;   // write g_h[(t+1)&1]
        __syncthreads();   // h stores happen-before release

        if (tid == 0) red_release_add(ctr);

        // ---- Y store overlaps the barrier wait
        yout[(size_t)t * HH] = yv;

        target += NNC;
        if (tid == 0) {
            while (ld_acquire(ctr) < target) { }
        }
        __syncthreads();   // all threads past the barrier
    }
}

// Final FC: out[b*T + t] = dot(Y0[b,t,:], fc_W) + fc_b. One warp per row.
__global__ void __launch_bounds__(256)
fc_kernel(const float* __restrict__ w, const float* __restrict__ bptr,
          float* __restrict__ out)
{
    int row  = blockIdx.x * 8 + (threadIdx.x >> 5);
    int lane = threadIdx.x & 31;
    const float* yr = g_Y0 + (size_t)row * HH;
    float4 a0 = *reinterpret_cast<const float4*>(yr + lane * 4);
    float4 a1 = *reinterpret_cast<const float4*>(yr + 128 + lane * 4);
    float4 w0 = *reinterpret_cast<const float4*>(w + lane * 4);
    float4 w1 = *reinterpret_cast<const float4*>(w + 128 + lane * 4);
    float s = a0.x * w0.x + a0.y * w0.y + a0.z * w0.z + a0.w * w0.w
            + a1.x * w1.x + a1.y * w1.y + a1.z * w1.z + a1.w * w1.w;
#pragma unroll
    for (int off = 16; off > 0; off >>= 1)
        s += __shfl_xor_sync(0xffffffffu, s, off);
    if (lane == 0) out[row] = s + bptr[0];
}

extern "C" void kernel_launch(void* const* d_in, const int* in_sizes, int n_in,
                              void* d_out, int out_size)
{
    const float* x        = (const float*)d_in[0];
    const float* Wih0     = (const float*)d_in[1];
    const float* Whh0     = (const float*)d_in[2];
    const float* Wih_rest = (const float*)d_in[3];
    const float* Whh_rest = (const float*)d_in[4];
    const float* bih      = (const float*)d_in[5];
    const float* bhh      = (const float*)d_in[6];
    const float* fcW      = (const float*)d_in[7];
    const float* fcb      = (const float*)d_in[8];
    float* out = (float*)d_out;

    size_t gsmem0 = (size_t)(128 * (DD + 4) + 64 * (DD + 4) + 64) * sizeof(float);
    size_t gsmem1 = (size_t)(128 * (HH + 4) + 64 * (HH + 4) + 64) * sizeof(float);
    size_t ssmem  = (size_t)(NR * KS + BSUB * KS + 2 * BSUB * HC) * sizeof(float); // ~86.5 KB

    cudaFuncSetAttribute(xg_gemm_kernel<DD>,
                         cudaFuncAttributeMaxDynamicSharedMemorySize, (int)gsmem0);
    cudaFuncSetAttribute(xg_gemm_kernel<HH>,
                         cudaFuncAttributeMaxDynamicSharedMemorySize, (int)gsmem1);
    cudaFuncSetAttribute(lstm_scan_kernel,
                         cudaFuncAttributeMaxDynamicSharedMemorySize, (int)ssmem);

    dim3 ggrid(G4H / 64, (BB * TT) / 128);   // 16 x 1024
    dim3 sgrid(NBG * NNC);                   // 128

    for (int l = 0; l < 5; ++l) {
        const float* bi = bih + (size_t)l * G4H;
        const float* bh = bhh + (size_t)l * G4H;
        if (l == 0) {
            xg_gemm_kernel<DD><<<ggrid, 256, gsmem0>>>(x, 0, Wih0, bi, bh);
        } else {
            int xsel = ((l - 1) & 1) == 0 ? 1 : 2;   // read Y0 for l=1,3 ; Y1 for l=2,4
            const float* Wih = Wih_rest + (size_t)(l - 1) * G4H * HH;
            xg_gemm_kernel<HH><<<ggrid, 256, gsmem1>>>(nullptr, xsel, Wih, bi, bh);
        }
        const float* Whh = (l == 0) ? Whh0 : (Whh_rest + (size_t)(l - 1) * G4H * HH);
        reset_kernel<<<1, 32>>>();
        lstm_scan_kernel<<<sgrid, NTHREADS, ssmem>>>(/*ysel=*/l & 1, Whh);
    }

    // Final layer (l=4) wrote Y0. FC head: [B*T] rows, one warp each.
    fc_kernel<<<(BB * TT) / 8, 256>>>(fcW, fcb, out);
}

// round 8
// speedup vs baseline: 3.6177x; 1.2151x over previous
#include <cuda_runtime.h>
#include <stdint.h>
#include <math.h>

// Problem constants
#define BB   128
#define TT   1024
#define DD   128
#define HH   256
#define G4H  1024

// Scan decomposition: 8 batch-groups x 16 N-slice CTAs = 128 CTAs
#define NBG  8
#define NNC  16
#define BSUB 16          // batch rows per CTA  (128/8)
#define HC   16          // h columns per CTA   (256/16)
#define NR   64          // gate cols per CTA (j-major: p = j_local*4 + gate)
#define NTHREADS 256
#define KS   264         // scan smem row stride (words); KS % 32 == 8 (phase-conflict-free)

// Device scratch (static — no allocation allowed)
__device__ float    g_XG[(size_t)BB * TT * G4H]; // 512 MB precomputed input gates (+bias)
__device__ float    g_Y0[(size_t)BB * TT * HH];  // 128 MB ping
__device__ float    g_Y1[(size_t)BB * TT * HH];  // 128 MB pong
__device__ float    g_h[2][BB * HH];             // h (tf32, pair-interleaved), dbl buffer
__device__ unsigned g_flags[NBG][NNC * 8];       // per-CTA step flags (32B-spaced)

__global__ void reset_kernel() {
    reinterpret_cast<unsigned*>(g_flags)[threadIdx.x] = 0u;   // NBG*NNC*8 threads
}

__device__ __forceinline__ float to_tf32(float x) {
    float r;
    asm("cvt.rna.tf32.f32 %0, %1;" : "=f"(r) : "f"(x));
    return r;
}

__device__ __forceinline__ float sigf(float x) {
    return 1.f / (1.f + __expf(-x));
}
__device__ __forceinline__ float tanh_fast(float x) {
    return 2.f / (1.f + __expf(-2.f * x)) - 1.f;
}

__device__ __forceinline__ void mma_tf32(float& c0, float& c1, float& c2, float& c3,
                                         uint32_t a0, uint32_t a1, uint32_t a2, uint32_t a3,
                                         uint32_t b0, uint32_t b1) {
    asm volatile(
        "mma.sync.aligned.m16n8k8.row.col.f32.tf32.tf32.f32 "
        "{%0,%1,%2,%3}, {%4,%5,%6,%7}, {%8,%9}, {%0,%1,%2,%3};\n"
        : "+f"(c0), "+f"(c1), "+f"(c2), "+f"(c3)
        : "r"(a0), "r"(a1), "r"(a2), "r"(a3), "r"(b0), "r"(b1));
}

__device__ __forceinline__ void st_release(unsigned* p, unsigned v) {
    asm volatile("st.release.gpu.global.u32 [%0], %1;" :: "l"(p), "r"(v) : "memory");
}
__device__ __forceinline__ unsigned ld_acquire(unsigned* p) {
    unsigned v;
    asm volatile("ld.acquire.gpu.global.u32 %0, [%1];" : "=r"(v) : "l"(p) : "memory");
    return v;
}

// pair-interleaved slot within an 8-block: logical k -> slot ((k&3)*2) | ((k>>2)&1)
__device__ __forceinline__ int kslot(int k) {
    return (k & ~7) + (((k & 3) << 1) | ((k >> 2) & 1));
}

// ============================================================================
// xg GEMM v2: g_XG[m, P] = sum_k In[m,k]*Wih[perm(P),k] + bias[perm(P)]
// P j-major permuted: perm(P) = (P&3)*HH + (P>>2).
// CTA tile 128m x 256n, K in 128-wide chunks resident in smem.
// 8 warps = 2(m) x 4(n), warp tile m64 x n64. Stride 136 -> conflict-free.
// ============================================================================
template <int K>
__global__ void __launch_bounds__(256, 1)
xg_gemm_kernel(const float* __restrict__ xext, int xsel,
               const float* __restrict__ Wih,
               const float* __restrict__ bih, const float* __restrict__ bhh)
{
    constexpr int KC  = 128;
    constexpr int KSg = KC + 8;               // 136; mod 32 == 8 -> phase-conflict-free
    extern __shared__ float sm[];
    float* As   = sm;                         // [128][136]
    float* Bs   = As + 128 * KSg;             // [256][136]
    float* bias = Bs + 256 * KSg;             // [256]

    const float* In = (xsel == 0) ? xext : ((xsel == 1) ? g_Y0 : g_Y1);
    const int m0  = blockIdx.y * 128;
    const int n0  = blockIdx.x * 256;
    const int tid = threadIdx.x;

    if (tid < 256) {
        int P  = n0 + tid;
        int bx = (P & 3) * HH + (P >> 2);
        bias[tid] = bih[bx] + bhh[bx];
    }

    const int lane = tid & 31, wid = tid >> 5;
    const int wm = wid >> 2, wn = wid & 3;     // 2(m) x 4(n)
    const int grp = lane >> 2, tg = lane & 3;

    float acc[4][8][4];
#pragma unroll
    for (int mi = 0; mi < 4; ++mi)
#pragma unroll
        for (int ni = 0; ni < 8; ++ni)
#pragma unroll
            for (int q = 0; q < 4; ++q) acc[mi][ni][q] = 0.f;

    const uint32_t* Ap = reinterpret_cast<const uint32_t*>(&As[(wm * 64 + grp) * KSg + tg]);
    const uint32_t* Bp = reinterpret_cast<const uint32_t*>(&Bs[(wn * 64 + grp) * KSg + tg]);

    for (int kc = 0; kc < K / KC; ++kc) {
        __syncthreads();   // protect smem from previous chunk's readers
        // ---- load As: 128 x 128 floats (tf32-rounded), coalesced float4
        for (int idx = tid; idx < 128 * 32; idx += 256) {
            int r = idx >> 5, k4 = idx & 31;
            float4 v = *reinterpret_cast<const float4*>(
                In + (size_t)(m0 + r) * K + kc * KC + k4 * 4);
            v.x = to_tf32(v.x); v.y = to_tf32(v.y); v.z = to_tf32(v.z); v.w = to_tf32(v.w);
            *reinterpret_cast<float4*>(&As[r * KSg + k4 * 4]) = v;
        }
        // ---- load Bs: 256 x 128 floats from permuted Wih rows
        for (int idx = tid; idx < 256 * 32; idx += 256) {
            int n = idx >> 5, k4 = idx & 31;
            int P  = n0 + n;
            int rw = (P & 3) * HH + (P >> 2);
            float4 v = *reinterpret_cast<const float4*>(
                Wih + (size_t)rw * K + kc * KC + k4 * 4);
            v.x = to_tf32(v.x); v.y = to_tf32(v.y); v.z = to_tf32(v.z); v.w = to_tf32(v.w);
            *reinterpret_cast<float4*>(&Bs[n * KSg + k4 * 4]) = v;
        }
        __syncthreads();

        // ---- warp m64 x n64 over this k-chunk
#pragma unroll
        for (int kt = 0; kt < KC / 8; ++kt) {
            uint32_t a[4][4];
#pragma unroll
            for (int mi = 0; mi < 4; ++mi) {
                const uint32_t* p = Ap + mi * 16 * KSg + kt * 8;
                a[mi][0] = p[0]; a[mi][1] = p[8 * KSg];
                a[mi][2] = p[4]; a[mi][3] = p[8 * KSg + 4];
            }
#pragma unroll
            for (int ni = 0; ni < 8; ++ni) {
                const uint32_t* q = Bp + ni * 8 * KSg + kt * 8;
                uint32_t b0 = q[0], b1 = q[4];
#pragma unroll
                for (int mi = 0; mi < 4; ++mi)
                    mma_tf32(acc[mi][ni][0], acc[mi][ni][1], acc[mi][ni][2], acc[mi][ni][3],
                             a[mi][0], a[mi][1], a[mi][2], a[mi][3], b0, b1);
            }
        }
    }

    // ---- epilogue: add bias, write float2 pairs
#pragma unroll
    for (int mi = 0; mi < 4; ++mi)
#pragma unroll
        for (int ni = 0; ni < 8; ++ni) {
            int rl = wm * 64 + mi * 16 + grp;
            int cl = wn * 64 + ni * 8 + 2 * tg;
            float b0 = bias[cl], b1 = bias[cl + 1];
            size_t o = (size_t)(m0 + rl) * G4H + (n0 + cl);
            *reinterpret_cast<float2*>(&g_XG[o]) =
                make_float2(acc[mi][ni][0] + b0, acc[mi][ni][1] + b1);
            *reinterpret_cast<float2*>(&g_XG[o + (size_t)8 * G4H]) =
                make_float2(acc[mi][ni][2] + b0, acc[mi][ni][3] + b1);
        }
}

// ============================================================================
// LSTM scan: per step Whh*h via tensor cores; xg preloaded (prefetched t+1).
// Flag-based barrier: each CTA st.release its own flag; warp 0 polls all 16.
// ============================================================================
__global__ void __launch_bounds__(NTHREADS, 1)
lstm_scan_kernel(int ysel, const float* __restrict__ Whh)
{
    extern __shared__ float sm[];
    float* Wsm = sm;              // [NR][KS]   tf32 weight slab (staging for reg load)
    float* Usm = Wsm + NR * KS;   // [BSUB][KS] h_{t-1} (tf32, pair-interleaved)
    float* Hs  = Usm + BSUB * KS; // [BSUB*HC]  tf32-interleaved h bounce

    float* Ydst = (ysel == 0) ? g_Y0 : g_Y1;

    const int cta = blockIdx.x;
    const int bg  = cta / NNC;
    const int nc  = cta % NNC;
    const int rb0 = bg * BSUB;
    const int tid = threadIdx.x;
    unsigned* myflag = &g_flags[bg][nc * 8];

    // ---- Weight slab (j-major permuted rows, pair-interleaved k), tf32
    for (int idx = tid; idx < NR * HH; idx += NTHREADS) {
        int rl = idx >> 8, k = idx & 255;
        int rw = (rl & 3) * HH + (nc * HC + (rl >> 2));
        Wsm[rl * KS + kslot(k)] = to_tf32(Whh[(size_t)rw * HH + k]);
    }
    // ---- Zero Usm (h_{-1} = 0)
    for (int idx = tid * 4; idx < BSUB * KS; idx += NTHREADS * 4)
        *reinterpret_cast<float4*>(&Usm[idx]) = make_float4(0.f, 0.f, 0.f, 0.f);
    __syncthreads();

    const int lane = tid & 31, wid = tid >> 5;     // wid = n8-tile index (0..7)
    const int grp = lane >> 2, tg = lane & 3;

    const uint32_t* Ua0 = reinterpret_cast<const uint32_t*>(&Usm[grp * KS + 2 * tg]);
    const uint32_t* Ua1 = Ua0 + 8 * KS;
    const uint32_t* Wb  = reinterpret_cast<const uint32_t*>(&Wsm[(wid * 8 + grp) * KS + 2 * tg]);

    // ---- Hoist W fragments into registers (32 k-blocks x uint2)
    uint2 wreg[32];
#pragma unroll
    for (int ib = 0; ib < 32; ++ib)
        wreg[ib] = *reinterpret_cast<const uint2*>(Wb + ib * 8);

    const int bA   = rb0 + grp;                    // batch row of accum rows c0,c1
    const int colP = nc * NR + wid * 8 + 2 * tg;   // permuted gate column of c0
    const float* xgA = g_XG + (size_t)bA * TT * G4H + colP;
    const float* xgB = xgA + (size_t)8 * TT * G4H; // batch row bA+8 (c2,c3)

    const bool odd  = (tg & 1);
    const int bl    = grp + (odd ? 8 : 0);         // local batch row this lane owns
    const int jl    = 2 * wid + (tg >> 1);         // local h-col this lane owns
    const int jslot = (jl & ~7) + (((jl & 3) << 1) | ((jl >> 2) & 1)); // interleaved slot

    // coalesced-store mapping: thread i -> (b = i>>4, col-slot = i&15)
    const int sb = tid >> 4, sj = tid & 15;
    float* hout0 = &g_h[0][(rb0 + sb) * HH + nc * HC + sj];
    float* hout1 = &g_h[1][(rb0 + sb) * HH + nc * HC + sj];
    // scattered Y store by owner (off critical path)
    float* yown  = &Ydst[(size_t)(rb0 + bl) * TT * HH + nc * HC + jl];

    // staging mapping: thread -> row (tid>>4), 16 cols starting at (tid&15)*16
    const int strow = tid >> 4;
    const int stk0  = (tid & 15) * 16;

    float c_state = 0.f;

    // preload xg for t = 0
    float2 x01 = *reinterpret_cast<const float2*>(xgA);
    float2 x23 = *reinterpret_cast<const float2*>(xgB);

    for (int t = 0; t < TT; ++t) {
        // ---- Stage h_{t-1} -> Usm : verbatim float4 copy (already tf32+interleaved)
        if (t > 0) {
            const float* hrow = g_h[t & 1] + (size_t)(rb0 + strow) * HH + stk0;
            float* urow = &Usm[strow * KS + stk0];
#pragma unroll
            for (int q = 0; q < 4; ++q) {
                float4 v = __ldcg(reinterpret_cast<const float4*>(hrow + q * 4));
                *reinterpret_cast<float4*>(urow + q * 4) = v;
            }
        }
        __syncthreads();   // Usm ready (also covers init at t=0)

        // ---- Whh * h_{t-1}: m16 x n8, K=256 as 4 independent chains, W in regs
        float a0c[4], a1c[4], a2c[4], a3c[4];
        a0c[0] = x01.x; a1c[0] = x01.y; a2c[0] = x23.x; a3c[0] = x23.y;
#pragma unroll
        for (int c = 1; c < 4; ++c) { a0c[c] = 0.f; a1c[c] = 0.f; a2c[c] = 0.f; a3c[c] = 0.f; }

#pragma unroll
        for (int kk = 0; kk < 8; ++kk) {
#pragma unroll
            for (int c = 0; c < 4; ++c) {
                int ib = c * 8 + kk;
                uint2 u0 = *reinterpret_cast<const uint2*>(Ua0 + ib * 8);
                uint2 u1 = *reinterpret_cast<const uint2*>(Ua1 + ib * 8);
                mma_tf32(a0c[c], a1c[c], a2c[c], a3c[c],
                         u0.x, u1.x, u0.y, u1.y, wreg[ib].x, wreg[ib].y);
            }
        }
        float c0 = (a0c[0] + a0c[1]) + (a0c[2] + a0c[3]);
        float c1 = (a1c[0] + a1c[1]) + (a1c[2] + a1c[3]);
        float c2 = (a2c[0] + a2c[1]) + (a2c[2] + a2c[3]);
        float c3 = (a3c[0] + a3c[1]) + (a3c[2] + a3c[3]);

        // ---- Gate exchange within lane pair (tg, tg^1)
        float s0 = odd ? c0 : c2;
        float s1 = odd ? c1 : c3;
        float r0 = __shfl_xor_sync(0xffffffffu, s0, 1);
        float r1 = __shfl_xor_sync(0xffffffffu, s1, 1);
        float iv = odd ? r0 : c0;
        float fv = odd ? r1 : c1;
        float gv = odd ? c2 : r0;
        float ov = odd ? c3 : r1;

        float is = sigf(iv);
        float fs = sigf(fv);
        float gt = tanh_fast(gv);
        float os = sigf(ov);
        c_state = fs * c_state + is * gt;
        float hn = os * tanh_fast(c_state);

        Hs[bl * HC + jslot] = to_tf32(hn);   // interleaved tf32 (for recurrence)
        __syncthreads();   // bounce complete

        // ---- Coalesced h store (64B row segments, pre-interleaved tf32)
        float hv = Hs[sb * HC + sj];
        if (t & 1) hout0[0] = hv; else hout1[0] = hv;   // write g_h[(t+1)&1]
        __syncthreads();   // h stores happen-before release

        if (tid == 0) st_release(myflag, (unsigned)(t + 1));

        // ---- Off-path work overlaps the barrier: Y store + xg prefetch
        yown[(size_t)t * HH] = hn;
        if (t + 1 < TT) {
            xgA += G4H; xgB += G4H;
            x01 = *reinterpret_cast<const float2*>(xgA);
            x23 = *reinterpret_cast<const float2*>(xgB);
        }

        // ---- Poll all 16 group flags (warp 0)
        if (wid == 0) {
            const unsigned tgt = (unsigned)(t + 1);
            bool done;
            do {
                unsigned v = 0xffffffffu;
                if (lane < NNC) v = ld_acquire(&g_flags[bg][lane * 8]);
                done = __all_sync(0xffffffffu, v >= tgt);
            } while (!done);
        }
        __syncthreads();
    }
}

// Final FC: out[b*T + t] = dot(Y0[b,t,:], fc_W) + fc_b. One warp per row.
__global__ void __launch_bounds__(256)
fc_kernel(const float* __restrict__ w, const float* __restrict__ bptr,
          float* __restrict__ out)
{
    int row  = blockIdx.x * 8 + (threadIdx.x >> 5);
    int lane = threadIdx.x & 31;
    const float* yr = g_Y0 + (size_t)row * HH;
    float4 a0 = *reinterpret_cast<const float4*>(yr + lane * 4);
    float4 a1 = *reinterpret_cast<const float4*>(yr + 128 + lane * 4);
    float4 w0 = *reinterpret_cast<const float4*>(w + lane * 4);
    float4 w1 = *reinterpret_cast<const float4*>(w + 128 + lane * 4);
    float s = a0.x * w0.x + a0.y * w0.y + a0.z * w0.z + a0.w * w0.w
            + a1.x * w1.x + a1.y * w1.y + a1.z * w1.z + a1.w * w1.w;
#pragma unroll
    for (int off = 16; off > 0; off >>= 1)
        s += __shfl_xor_sync(0xffffffffu, s, off);
    if (lane == 0) out[row] = s + bptr[0];
}

extern "C" void kernel_launch(void* const* d_in, const int* in_sizes, int n_in,
                              void* d_out, int out_size)
{
    const float* x        = (const float*)d_in[0];
    const float* Wih0     = (const float*)d_in[1];
    const float* Whh0     = (const float*)d_in[2];
    const float* Wih_rest = (const float*)d_in[3];
    const float* Whh_rest = (const float*)d_in[4];
    const float* bih      = (const float*)d_in[5];
    const float* bhh      = (const float*)d_in[6];
    const float* fcW      = (const float*)d_in[7];
    const float* fcb      = (const float*)d_in[8];
    float* out = (float*)d_out;

    size_t gsmem = (size_t)(128 * 136 + 256 * 136 + 256) * sizeof(float);     // ~205 KB
    size_t ssmem = (size_t)(NR * KS + BSUB * KS + BSUB * HC) * sizeof(float); // ~85.5 KB

    cudaFuncSetAttribute(xg_gemm_kernel<DD>,
                         cudaFuncAttributeMaxDynamicSharedMemorySize, (int)gsmem);
    cudaFuncSetAttribute(xg_gemm_kernel<HH>,
                         cudaFuncAttributeMaxDynamicSharedMemorySize, (int)gsmem);
    cudaFuncSetAttribute(lstm_scan_kernel,
                         cudaFuncAttributeMaxDynamicSharedMemorySize, (int)ssmem);

    dim3 ggrid(G4H / 256, (BB * TT) / 128);   // 4 x 1024
    dim3 sgrid(NBG * NNC);                    // 128

    for (int l = 0; l < 5; ++l) {
        const float* bi = bih + (size_t)l * G4H;
        const float* bh = bhh + (size_t)l * G4H;
        if (l == 0) {
            xg_gemm_kernel<DD><<<ggrid, 256, gsmem>>>(x, 0, Wih0, bi, bh);
        } else {
            int xsel = ((l - 1) & 1) == 0 ? 1 : 2;   // read Y0 for l=1,3 ; Y1 for l=2,4
            const float* Wih = Wih_rest + (size_t)(l - 1) * G4H * HH;
            xg_gemm_kernel<HH><<<ggrid, 256, gsmem>>>(nullptr, xsel, Wih, bi, bh);
        }
        const float* Whh = (l == 0) ? Whh0 : (Whh_rest + (size_t)(l - 1) * G4H * HH);
        reset_kernel<<<1, NBG * NNC * 8>>>();
        lstm_scan_kernel<<<sgrid, NTHREADS, ssmem>>>(/*ysel=*/l & 1, Whh);
    }

    // Final layer (l=4) wrote Y0. FC head: [B*T] rows, one warp each.
    fc_kernel<<<(BB * TT) / 8, 256>>>(fcW, fcb, out);
}